// round 2
// baseline (speedup 1.0000x reference)
#include <cuda_runtime.h>
#include <cstdint>

// ---------------------------------------------------------------------------
// Problem constants
// ---------------------------------------------------------------------------
#define BB 65536
static constexpr float LRELU = 0.01f;
static constexpr float LOG_SQRT_2PI_C = 0.91893853320467274178f;

// ---------------------------------------------------------------------------
// Device scratch (allocation-free rule: __device__ globals)
// ---------------------------------------------------------------------------
__device__ float g_S1[(size_t)BB * 512];      // 134 MB
__device__ float g_T1[(size_t)BB * 256];      //  67 MB
__device__ float g_H [(size_t)8 * BB * 256];  // 536 MB
__device__ float g_PS[(size_t)8 * BB * 40];   //  84 MB
__device__ float g_SG[(size_t)BB * 256];      //  67 MB

// ---------------------------------------------------------------------------
// Packed f32x2 helpers (Blackwell FFMA2: 2x fp32 FMA throughput, exact fp32)
// ---------------------------------------------------------------------------
__device__ __forceinline__ unsigned long long pk2(float lo, float hi) {
    unsigned long long r;
    asm("mov.b64 %0, {%1, %2};" : "=l"(r) : "f"(lo), "f"(hi));
    return r;
}
__device__ __forceinline__ void upk2(unsigned long long v, float& lo, float& hi) {
    asm("mov.b64 {%0, %1}, %2;" : "=f"(lo), "=f"(hi) : "l"(v));
}
__device__ __forceinline__ unsigned long long ffma2(unsigned long long a,
                                                    unsigned long long b,
                                                    unsigned long long c) {
    unsigned long long d;
    asm("fma.rn.f32x2 %0, %1, %2, %3;" : "=l"(d) : "l"(a), "l"(b), "l"(c));
    return d;
}

// ---------------------------------------------------------------------------
// Generic tiled SGEMM:  C[m,n] = act( A[m,:] @ W[:,n] + bias[n] )
//   A: (M x K) row-major with stride lda      (M is always BB here)
//   W: (K x N) row-major (stride N)
//   C: row stride ldc
//   BM=128, BN=64, BK=16, 256 threads, 8x4 per-thread microtile (f32x2 on N)
//   Requires: K % 16 == 0, lda % 4 == 0, n-tail guarded (N=40 case).
// ---------------------------------------------------------------------------
constexpr int BM = 128, BN = 64, BK = 16, ASTR = BM + 4;

__global__ __launch_bounds__(256) void gemm_bias_act(
    const float* __restrict__ A, int lda,
    const float* __restrict__ W,
    const float* __restrict__ bias,
    float* __restrict__ C, int ldc,
    int N, int K, int act)
{
    __shared__ float As[BK * ASTR];
    __shared__ float Bs[BK * BN];

    const int t  = threadIdx.x;
    const int tx = t & 15;        // 16 col-groups of 4
    const int ty = t >> 4;        // 16 row-groups of 8
    const int m0 = blockIdx.y * BM;
    const int n0 = blockIdx.x * BN;

    // A-tile load mapping: thread -> (row, 4-col chunk), 2 rows per thread
    const int ar  = t >> 2;           // 0..63
    const int ac4 = (t & 3) * 4;      // 0,4,8,12
    // B-tile load mapping
    const int br = t >> 4;            // 0..15
    const int bc = (t & 15) * 4;      // 0..60

    const float* Arow0 = A + (size_t)(m0 + ar) * lda;
    const float* Arow1 = A + (size_t)(m0 + ar + 64) * lda;

    unsigned long long acc[8][2];
#pragma unroll
    for (int i = 0; i < 8; i++) { acc[i][0] = 0ull; acc[i][1] = 0ull; }

    for (int k0 = 0; k0 < K; k0 += BK) {
        // global loads first (overlap with previous compute epilogue)
        float4 a0 = *(const float4*)(Arow0 + k0 + ac4);
        float4 a1 = *(const float4*)(Arow1 + k0 + ac4);
        float4 bv;
        {
            int n = n0 + bc;
            const float* wr = W + (size_t)(k0 + br) * N;
            if (n + 3 < N) {
                bv = *(const float4*)(wr + n);
            } else {
                bv.x = (n     < N) ? wr[n]     : 0.f;
                bv.y = (n + 1 < N) ? wr[n + 1] : 0.f;
                bv.z = (n + 2 < N) ? wr[n + 2] : 0.f;
                bv.w = (n + 3 < N) ? wr[n + 3] : 0.f;
            }
        }
        __syncthreads();   // previous tile fully consumed
        As[(ac4 + 0) * ASTR + ar]      = a0.x;
        As[(ac4 + 1) * ASTR + ar]      = a0.y;
        As[(ac4 + 2) * ASTR + ar]      = a0.z;
        As[(ac4 + 3) * ASTR + ar]      = a0.w;
        As[(ac4 + 0) * ASTR + ar + 64] = a1.x;
        As[(ac4 + 1) * ASTR + ar + 64] = a1.y;
        As[(ac4 + 2) * ASTR + ar + 64] = a1.z;
        As[(ac4 + 3) * ASTR + ar + 64] = a1.w;
        *(float4*)&Bs[br * BN + bc] = bv;
        __syncthreads();

#pragma unroll
        for (int kk = 0; kk < BK; kk++) {
            const float* ap = &As[kk * ASTR + ty * 8];
            float4 x0 = *(const float4*)ap;
            float4 x1 = *(const float4*)(ap + 4);
            float4 b  = *(const float4*)&Bs[kk * BN + tx * 4];
            unsigned long long b01 = pk2(b.x, b.y);
            unsigned long long b23 = pk2(b.z, b.w);
            float av[8] = {x0.x, x0.y, x0.z, x0.w, x1.x, x1.y, x1.z, x1.w};
#pragma unroll
            for (int m = 0; m < 8; m++) {
                unsigned long long am = pk2(av[m], av[m]);
                acc[m][0] = ffma2(am, b01, acc[m][0]);
                acc[m][1] = ffma2(am, b23, acc[m][1]);
            }
        }
    }

    // epilogue
    const int cn = n0 + tx * 4;
    float bvals[4];
#pragma unroll
    for (int j = 0; j < 4; j++)
        bvals[j] = (cn + j < N) ? bias[cn + j] : 0.f;

#pragma unroll
    for (int m = 0; m < 8; m++) {
        int row = m0 + ty * 8 + m;
        float v[4];
        upk2(acc[m][0], v[0], v[1]);
        upk2(acc[m][1], v[2], v[3]);
#pragma unroll
        for (int j = 0; j < 4; j++) {
            v[j] += bvals[j];
            if (act) v[j] = v[j] > 0.f ? v[j] : LRELU * v[j];
        }
        float* crow = C + (size_t)row * ldc;
        if (cn + 3 < N) {
            *(float4*)&crow[cn] = make_float4(v[0], v[1], v[2], v[3]);
        } else {
#pragma unroll
            for (int j = 0; j < 4; j++)
                if (cn + j < N) crow[cn + j] = v[j];
        }
    }
}

// ---------------------------------------------------------------------------
// Finalize: per row — lrelu(SG), gate = exp(sg@Wgate + bgate), mixture,
// log_prob + entropy. One warp per row.
// ---------------------------------------------------------------------------
__global__ __launch_bounds__(256) void finalize_kernel(
    const float* __restrict__ SG, const float* __restrict__ PS,
    const float* __restrict__ actions,
    const float* __restrict__ Wgate, const float* __restrict__ bgate,
    float* __restrict__ out)
{
    __shared__ float Wg_s[8 * 256];   // transposed: [p][k]
    const int t = threadIdx.x;
    for (int i = t; i < 2048; i += 256) {
        int k = i >> 3, p = i & 7;
        Wg_s[p * 256 + k] = Wgate[i];
    }
    __syncthreads();

    const int warp = t >> 5, lane = t & 31;
    const size_t row = (size_t)blockIdx.x * 8 + warp;

    // gate logits: sg (lrelu of SG row) dot Wgate columns
    float accp[8] = {0, 0, 0, 0, 0, 0, 0, 0};
#pragma unroll
    for (int i = 0; i < 8; i++) {
        float v = SG[row * 256 + lane + 32 * i];
        v = v > 0.f ? v : LRELU * v;
#pragma unroll
        for (int p = 0; p < 8; p++)
            accp[p] += v * Wg_s[p * 256 + lane + 32 * i];
    }
#pragma unroll
    for (int off = 16; off; off >>= 1)
#pragma unroll
        for (int p = 0; p < 8; p++)
            accp[p] += __shfl_xor_sync(0xffffffffu, accp[p], off);

    float wg[8];
#pragma unroll
    for (int p = 0; p < 8; p++)
        wg[p] = expf(accp[p] + bgate[p]);

    // mixture + log-prob terms: lanes 0..19 handle one action each
    float lp = 0.f, ent = 0.f;
    if (lane < 20) {
        float s1 = 0.f, s2 = 0.f;
#pragma unroll
        for (int p = 0; p < 8; p++) {
            const float* psr = PS + ((size_t)p * BB + row) * 40;
            float mu = psr[lane];
            float lg = psr[20 + lane];
            float inv = wg[p] * expf(-lg);   // wg / sigma
            s1 += mu * inv;
            s2 += inv;
        }
        float a = actions[row * 20 + lane];
        float z = (a - s1 / s2) * s2;        // (a - mu_net) / sigma_net
        float logsig = -logf(s2);            // log(sigma_net)
        lp  = -0.5f * z * z - logsig - LOG_SQRT_2PI_C;
        ent = 0.5f + LOG_SQRT_2PI_C + logsig;
    }
#pragma unroll
    for (int off = 16; off; off >>= 1) {
        lp  += __shfl_xor_sync(0xffffffffu, lp,  off);
        ent += __shfl_xor_sync(0xffffffffu, ent, off);
    }
    if (lane == 0) {
        out[row * 2]     = lp;
        out[row * 2 + 1] = ent;
    }
}

// ---------------------------------------------------------------------------
// Launcher
// ---------------------------------------------------------------------------
extern "C" void kernel_launch(void* const* d_in, const int* in_sizes, int n_in,
                              void* d_out, int out_size)
{
    const float* obs     = (const float*)d_in[0];
    const float* actions = (const float*)d_in[1];
    const float* W1      = (const float*)d_in[2];
    const float* b1      = (const float*)d_in[3];
    const float* W2      = (const float*)d_in[4];
    const float* b2      = (const float*)d_in[5];
    const float* Wp1     = (const float*)d_in[6];
    const float* bp1     = (const float*)d_in[7];
    const float* Wp2     = (const float*)d_in[8];
    const float* bp2     = (const float*)d_in[9];
    const float* Ws1     = (const float*)d_in[10];
    const float* bs1     = (const float*)d_in[11];
    const float* Ws2     = (const float*)d_in[12];
    const float* bs2     = (const float*)d_in[13];
    const float* Ws3     = (const float*)d_in[14];
    const float* bs3     = (const float*)d_in[15];
    const float* Wg1     = (const float*)d_in[16];
    const float* bg1     = (const float*)d_in[17];
    const float* Wg2     = (const float*)d_in[18];
    const float* bg2     = (const float*)d_in[19];
    const float* Wg3     = (const float*)d_in[20];
    const float* bg3     = (const float*)d_in[21];
    const float* Wgate   = (const float*)d_in[22];
    const float* bgate   = (const float*)d_in[23];

    float *S1, *T1, *H, *PS, *SG;
    cudaGetSymbolAddress((void**)&S1, g_S1);
    cudaGetSymbolAddress((void**)&T1, g_T1);
    cudaGetSymbolAddress((void**)&H,  g_H);
    cudaGetSymbolAddress((void**)&PS, g_PS);
    cudaGetSymbolAddress((void**)&SG, g_SG);

    dim3 blk(256);
    auto grid = [](int N) { return dim3((unsigned)((N + BN - 1) / BN), BB / BM); };

    // trunk
    gemm_bias_act<<<grid(512), blk>>>(obs, 384, W1, b1, S1, 512, 512, 256, 1);
    gemm_bias_act<<<grid(256), blk>>>(S1, 512, W2, b2, T1, 256, 256, 512, 1);

    // primitive heads
    for (int p = 0; p < 8; p++) {
        gemm_bias_act<<<grid(256), blk>>>(T1, 256,
            Wp1 + (size_t)p * 256 * 256, bp1 + (size_t)p * 256,
            H + (size_t)p * BB * 256, 256, 256, 256, 1);
    }
    for (int p = 0; p < 8; p++) {
        gemm_bias_act<<<grid(40), blk>>>(H + (size_t)p * BB * 256, 256,
            Wp2 + (size_t)p * 256 * 40, bp2 + (size_t)p * 40,
            PS + (size_t)p * BB * 40, 40, 40, 256, 0);
    }

    // gating branch (stat)
    gemm_bias_act<<<grid(512), blk>>>(obs, 384, Ws1, bs1, S1, 512, 512, 256, 1);
    gemm_bias_act<<<grid(256), blk>>>(S1, 512, Ws2, bs2, T1, 256, 256, 512, 1);
    gemm_bias_act<<<grid(128), blk>>>(T1, 256, Ws3, bs3, SG, 256, 128, 256, 0);

    // gating branch (goal)
    gemm_bias_act<<<grid(512), blk>>>(obs + 256, 384, Wg1, bg1, S1, 512, 512, 128, 1);
    gemm_bias_act<<<grid(256), blk>>>(S1, 512, Wg2, bg2, T1, 256, 256, 512, 1);
    gemm_bias_act<<<grid(128), blk>>>(T1, 256, Wg3, bg3, SG + 128, 256, 128, 256, 0);

    // finalize
    finalize_kernel<<<BB / 8, blk>>>(SG, PS, actions, Wgate, bgate, (float*)d_out);
}

// round 4
// speedup vs baseline: 1.5283x; 1.5283x over previous
#include <cuda_runtime.h>
#include <cuda_bf16.h>
#include <cstdint>

// ---------------------------------------------------------------------------
// Problem constants
// ---------------------------------------------------------------------------
#define BB 65536
static constexpr float LRELU = 0.01f;
static constexpr float LOG_SQRT_2PI_C = 0.91893853320467274178f;

// ---------------------------------------------------------------------------
// Device scratch (allocation-free rule: __device__ globals)
// ---------------------------------------------------------------------------
__device__ float g_S1[(size_t)BB * 512];
__device__ float g_T1[(size_t)BB * 256];
__device__ float g_H [(size_t)8 * BB * 256];
__device__ float g_PS[(size_t)8 * BB * 40];
__device__ float g_SG[(size_t)BB * 256];

// ---------------------------------------------------------------------------
// PTX helpers (generic-target: ldmatrix + mma.sync, sm_80+)
// ---------------------------------------------------------------------------
__device__ __forceinline__ uint32_t smem_u32(const void* p) {
    uint32_t a;
    asm("{ .reg .u64 t; cvta.to.shared.u64 t, %1; cvt.u32.u64 %0, t; }"
        : "=r"(a) : "l"(p));
    return a;
}

__device__ __forceinline__ void ldsm4(uint32_t* r, uint32_t addr) {
    asm volatile("ldmatrix.sync.aligned.m8n8.x4.shared.b16 {%0,%1,%2,%3}, [%4];"
                 : "=r"(r[0]), "=r"(r[1]), "=r"(r[2]), "=r"(r[3]) : "r"(addr));
}
__device__ __forceinline__ void ldsm4t(uint32_t* r, uint32_t addr) {
    asm volatile("ldmatrix.sync.aligned.m8n8.x4.trans.shared.b16 {%0,%1,%2,%3}, [%4];"
                 : "=r"(r[0]), "=r"(r[1]), "=r"(r[2]), "=r"(r[3]) : "r"(addr));
}
__device__ __forceinline__ void mma_bf16(float* d, const uint32_t* a, const uint32_t* b) {
    asm volatile(
        "mma.sync.aligned.m16n8k16.row.col.f32.bf16.bf16.f32 "
        "{%0,%1,%2,%3}, {%4,%5,%6,%7}, {%8,%9}, {%0,%1,%2,%3};"
        : "+f"(d[0]), "+f"(d[1]), "+f"(d[2]), "+f"(d[3])
        : "r"(a[0]), "r"(a[1]), "r"(a[2]), "r"(a[3]), "r"(b[0]), "r"(b[1]));
}

__device__ __forceinline__ uint32_t pack_bf2(float a, float b) {
    __nv_bfloat162 h = __floats2bfloat162_rn(a, b);
    return *reinterpret_cast<uint32_t*>(&h);
}

// ---------------------------------------------------------------------------
// Split-bf16 tensor-core GEMM:  C[m,n] = act( A[m,:] @ W[:,n] + bias[n] )
//   A fp32 (M x K, row stride lda), W fp32 (K x N row-major), C fp32.
//   CTA tile 128x64, K-chunk 32. 8 warps (4m x 2n), warp tile 32x32.
//   2-term bf16 split (hi/lo), 3 mma products, lo*lo dropped (~2^-16 rel).
//   Requires K % 32 == 0, lda % 4 == 0. N-tail (N=40) guarded + zero-filled.
// ---------------------------------------------------------------------------
constexpr int AST = 40;   // A smem stride (halves): 8-row ldmatrix conflict-free
constexpr int BST = 72;   // B smem stride (halves): 8-row ldmatrix conflict-free

__global__ __launch_bounds__(256, 2) void gemm_mma(
    const float* __restrict__ A, int lda,
    const float* __restrict__ W, int N,
    const float* __restrict__ bias,
    float* __restrict__ C, int ldc,
    int K, int act)
{
    __shared__ __align__(16) uint16_t AsH[128 * AST];
    __shared__ __align__(16) uint16_t AsL[128 * AST];
    __shared__ __align__(16) uint16_t BsH[32 * BST];
    __shared__ __align__(16) uint16_t BsL[32 * BST];

    const int t    = threadIdx.x;
    const int lane = t & 31;
    const int wid  = t >> 5;
    const int wm   = wid & 3;       // warp row   (0..3) -> rows wm*32
    const int wn   = wid >> 2;      // warp col   (0..1) -> cols wn*32
    const int m0   = blockIdx.y * 128;
    const int n0   = blockIdx.x * 64;

    // global-load mappings
    const int arow = t >> 1;             // 0..127
    const int aks  = (t & 1) * 16;       // 0 / 16
    const int bkk  = t >> 3;             // 0..31
    const int bnc  = (t & 7) * 8;        // 0..56

    const float* Aptr = A + (size_t)(m0 + arow) * lda + aks;

    float acc[2][4][4];
#pragma unroll
    for (int i = 0; i < 2; i++)
#pragma unroll
        for (int j = 0; j < 4; j++)
#pragma unroll
            for (int q = 0; q < 4; q++) acc[i][j][q] = 0.f;

    const int nchunks = K >> 5;
    for (int c = 0; c < nchunks; c++) {
        const int k0 = c << 5;

        // ---- stage global loads in registers (overlap previous compute) ----
        float4 av[4];
#pragma unroll
        for (int j = 0; j < 4; j++)
            av[j] = *(const float4*)(Aptr + k0 + j * 4);

        float bvv[8];
        {
            const float* wr = W + (size_t)(k0 + bkk) * N + n0 + bnc;
#pragma unroll
            for (int j = 0; j < 2; j++) {
                if (n0 + bnc + j * 4 + 4 <= N) {
                    float4 v = *(const float4*)(wr + j * 4);
                    bvv[j * 4] = v.x; bvv[j * 4 + 1] = v.y;
                    bvv[j * 4 + 2] = v.z; bvv[j * 4 + 3] = v.w;
                } else {
#pragma unroll
                    for (int q = 0; q < 4; q++)
                        bvv[j * 4 + q] =
                            (n0 + bnc + j * 4 + q < N) ? wr[j * 4 + q] : 0.f;
                }
            }
        }

        __syncthreads();   // previous chunk fully consumed

        // ---- A: split fp32 -> hi/lo bf16, [m][k] layout ----
#pragma unroll
        for (int j = 0; j < 4; j++) {
            float v[4] = {av[j].x, av[j].y, av[j].z, av[j].w};
            float h[4], l[4];
#pragma unroll
            for (int q = 0; q < 4; q++) {
                h[q] = __bfloat162float(__float2bfloat16_rn(v[q]));
                l[q] = v[q] - h[q];
            }
            int idx = arow * AST + aks + j * 4;       // even -> u32 aligned
            uint32_t* dh = (uint32_t*)&AsH[idx];
            uint32_t* dl = (uint32_t*)&AsL[idx];
            dh[0] = pack_bf2(h[0], h[1]); dh[1] = pack_bf2(h[2], h[3]);
            dl[0] = pack_bf2(l[0], l[1]); dl[1] = pack_bf2(l[2], l[3]);
        }

        // ---- B: split, [k][n] layout (ldmatrix.trans consumes) ----
        {
            int idx = bkk * BST + bnc;
            uint32_t* dh = (uint32_t*)&BsH[idx];
            uint32_t* dl = (uint32_t*)&BsL[idx];
#pragma unroll
            for (int j = 0; j < 4; j++) {
                float x0 = bvv[j * 2], x1 = bvv[j * 2 + 1];
                float h0 = __bfloat162float(__float2bfloat16_rn(x0));
                float h1 = __bfloat162float(__float2bfloat16_rn(x1));
                dh[j] = pack_bf2(h0, h1);
                dl[j] = pack_bf2(x0 - h0, x1 - h1);
            }
        }

        __syncthreads();

        // ---- compute: 2 k16 steps ----
#pragma unroll
        for (int ks = 0; ks < 32; ks += 16) {
            uint32_t Ah[2][4], Al[2][4], Bh[4][2], Bl[4][2];

            // A fragments: lanes 0-15 rows, lanes 16-31 k+8
            {
                int r  = lane & 15;
                int kq = (lane >> 4) * 8;
#pragma unroll
                for (int mi = 0; mi < 2; mi++) {
                    int m = wm * 32 + mi * 16 + r;
                    ldsm4(Ah[mi], smem_u32(&AsH[m * AST + ks + kq]));
                    ldsm4(Al[mi], smem_u32(&AsL[m * AST + ks + kq]));
                }
            }
            // B fragments via trans: tiles (k0n0)(k8n0)(k0n8)(k8n8)
            {
                int g  = lane >> 3;
                int rr = lane & 7;
                int krow = ks + (g & 1) * 8 + rr;
                int ncol = (g >> 1) * 8;
#pragma unroll
                for (int h = 0; h < 2; h++) {
                    int nb = wn * 32 + h * 16 + ncol;
                    ldsm4t(&Bh[h * 2][0], smem_u32(&BsH[krow * BST + nb]));
                    ldsm4t(&Bl[h * 2][0], smem_u32(&BsL[krow * BST + nb]));
                }
            }

#pragma unroll
            for (int mi = 0; mi < 2; mi++)
#pragma unroll
                for (int ni = 0; ni < 4; ni++) {
                    mma_bf16(acc[mi][ni], Ah[mi], Bh[ni]);
                    mma_bf16(acc[mi][ni], Ah[mi], Bl[ni]);
                    mma_bf16(acc[mi][ni], Al[mi], Bh[ni]);
                }
        }
    }

    // ---- epilogue: bias + act + store ----
    const int r4 = lane >> 2;
    const int c2 = (lane & 3) * 2;
#pragma unroll
    for (int mi = 0; mi < 2; mi++) {
#pragma unroll
        for (int ni = 0; ni < 4; ni++) {
            int col = n0 + wn * 32 + ni * 8 + c2;
            if (col >= N) continue;
            int row = m0 + wm * 32 + mi * 16 + r4;
            float b0 = bias[col], b1 = bias[col + 1];
            float v0 = acc[mi][ni][0] + b0;
            float v1 = acc[mi][ni][1] + b1;
            float v2 = acc[mi][ni][2] + b0;
            float v3 = acc[mi][ni][3] + b1;
            if (act) {
                v0 = v0 > 0.f ? v0 : LRELU * v0;
                v1 = v1 > 0.f ? v1 : LRELU * v1;
                v2 = v2 > 0.f ? v2 : LRELU * v2;
                v3 = v3 > 0.f ? v3 : LRELU * v3;
            }
            *(float2*)&C[(size_t)row * ldc + col]       = make_float2(v0, v1);
            *(float2*)&C[(size_t)(row + 8) * ldc + col] = make_float2(v2, v3);
        }
    }
}

// ---------------------------------------------------------------------------
// Finalize: gate + mixture + log_prob/entropy (one warp per row)
// ---------------------------------------------------------------------------
__global__ __launch_bounds__(256) void finalize_kernel(
    const float* __restrict__ SG, const float* __restrict__ PS,
    const float* __restrict__ actions,
    const float* __restrict__ Wgate, const float* __restrict__ bgate,
    float* __restrict__ out)
{
    __shared__ float Wg_s[8 * 256];
    const int t = threadIdx.x;
    for (int i = t; i < 2048; i += 256) {
        int k = i >> 3, p = i & 7;
        Wg_s[p * 256 + k] = Wgate[i];
    }
    __syncthreads();

    const int warp = t >> 5, lane = t & 31;
    const size_t row = (size_t)blockIdx.x * 8 + warp;

    float accp[8] = {0, 0, 0, 0, 0, 0, 0, 0};
#pragma unroll
    for (int i = 0; i < 8; i++) {
        float v = SG[row * 256 + lane + 32 * i];
        v = v > 0.f ? v : LRELU * v;
#pragma unroll
        for (int p = 0; p < 8; p++)
            accp[p] += v * Wg_s[p * 256 + lane + 32 * i];
    }
#pragma unroll
    for (int off = 16; off; off >>= 1)
#pragma unroll
        for (int p = 0; p < 8; p++)
            accp[p] += __shfl_xor_sync(0xffffffffu, accp[p], off);

    float wg[8];
#pragma unroll
    for (int p = 0; p < 8; p++)
        wg[p] = expf(accp[p] + bgate[p]);

    float lp = 0.f, ent = 0.f;
    if (lane < 20) {
        float s1 = 0.f, s2 = 0.f;
#pragma unroll
        for (int p = 0; p < 8; p++) {
            const float* psr = PS + ((size_t)p * BB + row) * 40;
            float mu = psr[lane];
            float lg = psr[20 + lane];
            float inv = wg[p] * expf(-lg);
            s1 += mu * inv;
            s2 += inv;
        }
        float a = actions[row * 20 + lane];
        float z = (a - s1 / s2) * s2;
        float logsig = -logf(s2);
        lp  = -0.5f * z * z - logsig - LOG_SQRT_2PI_C;
        ent = 0.5f + LOG_SQRT_2PI_C + logsig;
    }
#pragma unroll
    for (int off = 16; off; off >>= 1) {
        lp  += __shfl_xor_sync(0xffffffffu, lp,  off);
        ent += __shfl_xor_sync(0xffffffffu, ent, off);
    }
    if (lane == 0) {
        out[row * 2]     = lp;
        out[row * 2 + 1] = ent;
    }
}

// ---------------------------------------------------------------------------
// Launcher
// ---------------------------------------------------------------------------
extern "C" void kernel_launch(void* const* d_in, const int* in_sizes, int n_in,
                              void* d_out, int out_size)
{
    const float* obs     = (const float*)d_in[0];
    const float* actions = (const float*)d_in[1];
    const float* W1      = (const float*)d_in[2];
    const float* b1      = (const float*)d_in[3];
    const float* W2      = (const float*)d_in[4];
    const float* b2      = (const float*)d_in[5];
    const float* Wp1     = (const float*)d_in[6];
    const float* bp1     = (const float*)d_in[7];
    const float* Wp2     = (const float*)d_in[8];
    const float* bp2     = (const float*)d_in[9];
    const float* Ws1     = (const float*)d_in[10];
    const float* bs1     = (const float*)d_in[11];
    const float* Ws2     = (const float*)d_in[12];
    const float* bs2     = (const float*)d_in[13];
    const float* Ws3     = (const float*)d_in[14];
    const float* bs3     = (const float*)d_in[15];
    const float* Wg1     = (const float*)d_in[16];
    const float* bg1     = (const float*)d_in[17];
    const float* Wg2     = (const float*)d_in[18];
    const float* bg2     = (const float*)d_in[19];
    const float* Wg3     = (const float*)d_in[20];
    const float* bg3     = (const float*)d_in[21];
    const float* Wgate   = (const float*)d_in[22];
    const float* bgate   = (const float*)d_in[23];

    float *S1, *T1, *H, *PS, *SG;
    cudaGetSymbolAddress((void**)&S1, g_S1);
    cudaGetSymbolAddress((void**)&T1, g_T1);
    cudaGetSymbolAddress((void**)&H,  g_H);
    cudaGetSymbolAddress((void**)&PS, g_PS);
    cudaGetSymbolAddress((void**)&SG, g_SG);

    dim3 blk(256);
    auto grid = [](int N) { return dim3((unsigned)((N + 63) / 64), BB / 128); };

    // trunk
    gemm_mma<<<grid(512), blk>>>(obs, 384, W1, 512, b1, S1, 512, 256, 1);
    gemm_mma<<<grid(256), blk>>>(S1, 512, W2, 256, b2, T1, 256, 512, 1);

    // primitive heads
    for (int p = 0; p < 8; p++) {
        gemm_mma<<<grid(256), blk>>>(T1, 256,
            Wp1 + (size_t)p * 256 * 256, 256, bp1 + (size_t)p * 256,
            H + (size_t)p * BB * 256, 256, 256, 1);
    }
    for (int p = 0; p < 8; p++) {
        gemm_mma<<<grid(40), blk>>>(H + (size_t)p * BB * 256, 256,
            Wp2 + (size_t)p * 256 * 40, 40, bp2 + (size_t)p * 40,
            PS + (size_t)p * BB * 40, 40, 256, 0);
    }

    // gating branch (stat)
    gemm_mma<<<grid(512), blk>>>(obs, 384, Ws1, 512, bs1, S1, 512, 256, 1);
    gemm_mma<<<grid(256), blk>>>(S1, 512, Ws2, 256, bs2, T1, 256, 512, 1);
    gemm_mma<<<grid(128), blk>>>(T1, 256, Ws3, 128, bs3, SG, 256, 256, 0);

    // gating branch (goal)
    gemm_mma<<<grid(512), blk>>>(obs + 256, 384, Wg1, 512, bg1, S1, 512, 128, 1);
    gemm_mma<<<grid(256), blk>>>(S1, 512, Wg2, 256, bg2, T1, 256, 512, 1);
    gemm_mma<<<grid(128), blk>>>(T1, 256, Wg3, 128, bg3, SG + 128, 256, 256, 0);

    // finalize
    finalize_kernel<<<BB / 8, blk>>>(SG, PS, actions, Wgate, bgate, (float*)d_out);
}

// round 5
// speedup vs baseline: 1.9146x; 1.2528x over previous
#include <cuda_runtime.h>
#include <cuda_bf16.h>
#include <cstdint>

// ---------------------------------------------------------------------------
// Problem constants
// ---------------------------------------------------------------------------
#define BB 65536
static constexpr float LRELU = 0.01f;
static constexpr float LOG_SQRT_2PI_C = 0.91893853320467274178f;

// ---------------------------------------------------------------------------
// Device scratch (allocation-free rule: __device__ globals)
// ---------------------------------------------------------------------------
// split activations (bf16 hi/lo planes)
__device__ uint16_t g_obsH[(size_t)BB * 384];
__device__ uint16_t g_obsL[(size_t)BB * 384];
__device__ uint16_t g_S1H[(size_t)BB * 512];
__device__ uint16_t g_S1L[(size_t)BB * 512];
__device__ uint16_t g_T1H[(size_t)BB * 256];
__device__ uint16_t g_T1L[(size_t)BB * 256];
__device__ uint16_t g_HH[(size_t)8 * BB * 256];
__device__ uint16_t g_HL[(size_t)8 * BB * 256];
// fp32 outputs consumed by finalize
__device__ float g_PS[(size_t)8 * BB * 40];
__device__ float g_SG[(size_t)BB * 256];
// split weights, [k][n] padded layout
static constexpr size_t WPOOL = 1441792;
__device__ uint16_t g_Wh[WPOOL];
__device__ uint16_t g_Wl[WPOOL];

// weight pool offsets
static constexpr size_t O_W1  = 0;         // 256x512
static constexpr size_t O_W2  = 131072;    // 512x256
static constexpr size_t O_Wp1 = 262144;    // 8 x 256x256
static constexpr size_t O_Wp2 = 786432;    // 8 x 256x64 (pad of 40)
static constexpr size_t O_Ws1 = 917504;    // 256x512
static constexpr size_t O_Ws2 = 1048576;   // 512x256
static constexpr size_t O_Ws3 = 1179648;   // 256x128
static constexpr size_t O_Wg1 = 1212416;   // 128x512
static constexpr size_t O_Wg2 = 1277952;   // 512x256
static constexpr size_t O_Wg3 = 1409024;   // 256x128

// ---------------------------------------------------------------------------
// PTX helpers
// ---------------------------------------------------------------------------
__device__ __forceinline__ uint32_t smem_u32(const void* p) {
    uint32_t a;
    asm("{ .reg .u64 t; cvta.to.shared.u64 t, %1; cvt.u32.u64 %0, t; }"
        : "=r"(a) : "l"(p));
    return a;
}
__device__ __forceinline__ void cpa16(uint32_t dst, const void* src) {
    asm volatile("cp.async.cg.shared.global [%0], [%1], 16;"
                 :: "r"(dst), "l"(src) : "memory");
}
__device__ __forceinline__ void cp_commit() {
    asm volatile("cp.async.commit_group;" ::: "memory");
}
template <int N> __device__ __forceinline__ void cp_wait() {
    asm volatile("cp.async.wait_group %0;" :: "n"(N) : "memory");
}
__device__ __forceinline__ void ldsm4(uint32_t* r, uint32_t addr) {
    asm volatile("ldmatrix.sync.aligned.m8n8.x4.shared.b16 {%0,%1,%2,%3}, [%4];"
                 : "=r"(r[0]), "=r"(r[1]), "=r"(r[2]), "=r"(r[3]) : "r"(addr));
}
__device__ __forceinline__ void ldsm4t(uint32_t* r, uint32_t addr) {
    asm volatile("ldmatrix.sync.aligned.m8n8.x4.trans.shared.b16 {%0,%1,%2,%3}, [%4];"
                 : "=r"(r[0]), "=r"(r[1]), "=r"(r[2]), "=r"(r[3]) : "r"(addr));
}
__device__ __forceinline__ void mma_bf16(float* d, const uint32_t* a, const uint32_t* b) {
    asm volatile(
        "mma.sync.aligned.m16n8k16.row.col.f32.bf16.bf16.f32 "
        "{%0,%1,%2,%3}, {%4,%5,%6,%7}, {%8,%9}, {%0,%1,%2,%3};"
        : "+f"(d[0]), "+f"(d[1]), "+f"(d[2]), "+f"(d[3])
        : "r"(a[0]), "r"(a[1]), "r"(a[2]), "r"(a[3]), "r"(b[0]), "r"(b[1]));
}
__device__ __forceinline__ uint32_t pack_bf2(float a, float b) {
    __nv_bfloat162 h = __floats2bfloat162_rn(a, b);
    return *reinterpret_cast<uint32_t*>(&h);
}
__device__ __forceinline__ uint16_t bfh(float v) {
    __nv_bfloat16 h = __float2bfloat16_rn(v);
    return *reinterpret_cast<uint16_t*>(&h);
}
__device__ __forceinline__ float bff(uint16_t u) {
    __nv_bfloat16 h = *reinterpret_cast<__nv_bfloat16*>(&u);
    return __bfloat162float(h);
}

// ---------------------------------------------------------------------------
// Prep kernels: split fp32 -> bf16 hi/lo planes
// ---------------------------------------------------------------------------
struct WDesc { const float* src; int N, Np; size_t off; int tot; };
struct WPack { WDesc d[10]; };

__global__ void prep_weights(WPack p) {
    for (int e = 0; e < 10; e++) {
        const WDesc w = p.d[e];
        for (int i = blockIdx.x * blockDim.x + threadIdx.x; i < w.tot;
             i += gridDim.x * blockDim.x) {
            int k = i / w.Np, n = i % w.Np;
            float v = (n < w.N) ? w.src[(size_t)k * w.N + n] : 0.f;
            uint16_t h = bfh(v);
            g_Wh[w.off + i] = h;
            g_Wl[w.off + i] = bfh(v - bff(h));
        }
    }
}

__global__ void prep_obs(const float* __restrict__ src, size_t n4) {
    size_t i = (size_t)blockIdx.x * blockDim.x + threadIdx.x;
    if (i >= n4) return;
    float4 v = ((const float4*)src)[i];
    float h0 = bff(bfh(v.x)), h1 = bff(bfh(v.y));
    float h2 = bff(bfh(v.z)), h3 = bff(bfh(v.w));
    uint32_t* dh = (uint32_t*)&g_obsH[i * 4];
    uint32_t* dl = (uint32_t*)&g_obsL[i * 4];
    dh[0] = pack_bf2(h0, h1); dh[1] = pack_bf2(h2, h3);
    dl[0] = pack_bf2(v.x - h0, v.y - h1); dl[1] = pack_bf2(v.z - h2, v.w - h3);
}

// ---------------------------------------------------------------------------
// Split-bf16 tensor-core GEMM with cp.async double buffering.
//   A: pre-split bf16 planes (M x K, stride lda halves)
//   B: pre-split bf16 planes, [k][n] padded to Np
//   CTA tile 128x64, K-chunk 32, 8 warps (4m x 2n), warp tile 32x32.
//   mode 0: fp32 out (col<Nreal guard); mode 1: split bf16 out.
// ---------------------------------------------------------------------------
constexpr int AST = 40;   // A smem stride (halves)
constexpr int BST = 72;   // B smem stride (halves)
// per-stage byte layout
constexpr int SM_AH = 0;
constexpr int SM_AL = 10240;
constexpr int SM_BH = 20480;
constexpr int SM_BL = 25088;
constexpr int SM_STAGE = 29696;
constexpr int SM_TOTAL = 2 * SM_STAGE;

__global__ void __launch_bounds__(256, 3) gemm_tc2(
    const uint16_t* __restrict__ Ah, const uint16_t* __restrict__ Al, int lda,
    const uint16_t* __restrict__ Bh, const uint16_t* __restrict__ Bl, int Np,
    const float* __restrict__ bias, int Nreal,
    float* __restrict__ Cf, uint16_t* __restrict__ Chi, uint16_t* __restrict__ Clo,
    int ldc, int K, int act, int mode)
{
    extern __shared__ __align__(16) char smem[];
    const uint32_t sb = smem_u32(smem);

    const int t    = threadIdx.x;
    const int lane = t & 31;
    const int wid  = t >> 5;
    const int wm   = wid & 3;
    const int wn   = wid >> 2;
    const int m0   = blockIdx.y * 128;
    const int n0   = blockIdx.x * 64;

    // copy mappings
    const int ar = t >> 1;                 // A: 128 rows, 2 thr/row
    const int as = (t & 1) * 2;            // seg pair 0/2
    const int br = t >> 3;                 // B: 32 rows
    const int bs = t & 7;                  // seg 0..7

    const uint16_t* Asrc_h = Ah + (size_t)(m0 + ar) * lda;
    const uint16_t* Asrc_l = Al + (size_t)(m0 + ar) * lda;
    const uint16_t* Bsrc_h = Bh + (size_t)br * Np + n0 + bs * 8;
    const uint16_t* Bsrc_l = Bl + (size_t)br * Np + n0 + bs * 8;

    auto issue = [&](int c, int buf) {
        const uint32_t base = sb + buf * SM_STAGE;
        const int k0 = c << 5;
        // A: 2 segs x 2 planes per thread
        uint32_t da = base + SM_AH + (ar * AST + as * 8) * 2;
        uint32_t dl = base + SM_AL + (ar * AST + as * 8) * 2;
        const uint16_t* sa = Asrc_h + k0 + as * 8;
        const uint16_t* sl = Asrc_l + k0 + as * 8;
        cpa16(da,      sa);
        cpa16(da + 16, sa + 8);
        cpa16(dl,      sl);
        cpa16(dl + 16, sl + 8);
        // B: 1 seg x 2 planes per thread
        uint32_t db = base + SM_BH + (br * BST + bs * 8) * 2;
        uint32_t dbl = base + SM_BL + (br * BST + bs * 8) * 2;
        cpa16(db,  Bsrc_h + (size_t)k0 * Np);
        cpa16(dbl, Bsrc_l + (size_t)k0 * Np);
    };

    float acc[2][4][4];
#pragma unroll
    for (int i = 0; i < 2; i++)
#pragma unroll
        for (int j = 0; j < 4; j++)
#pragma unroll
            for (int q = 0; q < 4; q++) acc[i][j][q] = 0.f;

    const int nch = K >> 5;
    issue(0, 0);
    cp_commit();

    for (int c = 0; c < nch; c++) {
        if (c + 1 < nch) {
            issue(c + 1, (c + 1) & 1);
            cp_commit();
            cp_wait<1>();
        } else {
            cp_wait<0>();
        }
        __syncthreads();

        const uint32_t base = sb + (c & 1) * SM_STAGE;
        const uint32_t aH = base + SM_AH, aL = base + SM_AL;
        const uint32_t bH = base + SM_BH, bL = base + SM_BL;

#pragma unroll
        for (int ks = 0; ks < 32; ks += 16) {
            uint32_t Afh[2][4], Afl[2][4], Bfh[4][2], Bfl[4][2];
            {
                int r  = lane & 15;
                int kq = (lane >> 4) * 8;
#pragma unroll
                for (int mi = 0; mi < 2; mi++) {
                    int m = wm * 32 + mi * 16 + r;
                    uint32_t off = (m * AST + ks + kq) * 2;
                    ldsm4(Afh[mi], aH + off);
                    ldsm4(Afl[mi], aL + off);
                }
            }
            {
                int g  = lane >> 3;
                int rr = lane & 7;
                int krow = ks + (g & 1) * 8 + rr;
                int ncol = (g >> 1) * 8;
#pragma unroll
                for (int h = 0; h < 2; h++) {
                    int nb = wn * 32 + h * 16 + ncol;
                    uint32_t off = (krow * BST + nb) * 2;
                    ldsm4t(&Bfh[h * 2][0], bH + off);
                    ldsm4t(&Bfl[h * 2][0], bL + off);
                }
            }
#pragma unroll
            for (int mi = 0; mi < 2; mi++)
#pragma unroll
                for (int ni = 0; ni < 4; ni++) {
                    mma_bf16(acc[mi][ni], Afh[mi], Bfh[ni]);
                    mma_bf16(acc[mi][ni], Afh[mi], Bfl[ni]);
                    mma_bf16(acc[mi][ni], Afl[mi], Bfh[ni]);
                }
        }
        __syncthreads();
    }

    // ---- epilogue ----
    const int r4 = lane >> 2;
    const int c2 = (lane & 3) * 2;
#pragma unroll
    for (int mi = 0; mi < 2; mi++) {
#pragma unroll
        for (int ni = 0; ni < 4; ni++) {
            int col = n0 + wn * 32 + ni * 8 + c2;
            int row = m0 + wm * 32 + mi * 16 + r4;
            if (mode == 0 && col >= Nreal) continue;
            float b0 = bias[col], b1 = bias[col + 1];
            float v0 = acc[mi][ni][0] + b0;
            float v1 = acc[mi][ni][1] + b1;
            float v2 = acc[mi][ni][2] + b0;
            float v3 = acc[mi][ni][3] + b1;
            if (act) {
                v0 = v0 > 0.f ? v0 : LRELU * v0;
                v1 = v1 > 0.f ? v1 : LRELU * v1;
                v2 = v2 > 0.f ? v2 : LRELU * v2;
                v3 = v3 > 0.f ? v3 : LRELU * v3;
            }
            if (mode == 0) {
                *(float2*)&Cf[(size_t)row * ldc + col]       = make_float2(v0, v1);
                *(float2*)&Cf[(size_t)(row + 8) * ldc + col] = make_float2(v2, v3);
            } else {
                float h0 = bff(bfh(v0)), h1 = bff(bfh(v1));
                float h2 = bff(bfh(v2)), h3 = bff(bfh(v3));
                size_t i0 = (size_t)row * ldc + col;
                size_t i1 = (size_t)(row + 8) * ldc + col;
                *(uint32_t*)&Chi[i0] = pack_bf2(h0, h1);
                *(uint32_t*)&Clo[i0] = pack_bf2(v0 - h0, v1 - h1);
                *(uint32_t*)&Chi[i1] = pack_bf2(h2, h3);
                *(uint32_t*)&Clo[i1] = pack_bf2(v2 - h2, v3 - h3);
            }
        }
    }
}

// ---------------------------------------------------------------------------
// Finalize: gate + mixture + log_prob/entropy (one warp per row)
// ---------------------------------------------------------------------------
__global__ __launch_bounds__(256) void finalize_kernel(
    const float* __restrict__ SG, const float* __restrict__ PS,
    const float* __restrict__ actions,
    const float* __restrict__ Wgate, const float* __restrict__ bgate,
    float* __restrict__ out)
{
    __shared__ float Wg_s[8 * 256];
    const int t = threadIdx.x;
    for (int i = t; i < 2048; i += 256) {
        int k = i >> 3, p = i & 7;
        Wg_s[p * 256 + k] = Wgate[i];
    }
    __syncthreads();

    const int warp = t >> 5, lane = t & 31;
    const size_t row = (size_t)blockIdx.x * 8 + warp;

    float accp[8] = {0, 0, 0, 0, 0, 0, 0, 0};
#pragma unroll
    for (int i = 0; i < 8; i++) {
        float v = SG[row * 256 + lane + 32 * i];
        v = v > 0.f ? v : LRELU * v;
#pragma unroll
        for (int p = 0; p < 8; p++)
            accp[p] += v * Wg_s[p * 256 + lane + 32 * i];
    }
#pragma unroll
    for (int off = 16; off; off >>= 1)
#pragma unroll
        for (int p = 0; p < 8; p++)
            accp[p] += __shfl_xor_sync(0xffffffffu, accp[p], off);

    float wg[8];
#pragma unroll
    for (int p = 0; p < 8; p++)
        wg[p] = expf(accp[p] + bgate[p]);

    float lp = 0.f, ent = 0.f;
    if (lane < 20) {
        float s1 = 0.f, s2 = 0.f;
#pragma unroll
        for (int p = 0; p < 8; p++) {
            const float* psr = PS + ((size_t)p * BB + row) * 40;
            float mu = psr[lane];
            float lg = psr[20 + lane];
            float inv = wg[p] * expf(-lg);
            s1 += mu * inv;
            s2 += inv;
        }
        float a = actions[row * 20 + lane];
        float z = (a - s1 / s2) * s2;
        float logsig = -logf(s2);
        lp  = -0.5f * z * z - logsig - LOG_SQRT_2PI_C;
        ent = 0.5f + LOG_SQRT_2PI_C + logsig;
    }
#pragma unroll
    for (int off = 16; off; off >>= 1) {
        lp  += __shfl_xor_sync(0xffffffffu, lp,  off);
        ent += __shfl_xor_sync(0xffffffffu, ent, off);
    }
    if (lane == 0) {
        out[row * 2]     = lp;
        out[row * 2 + 1] = ent;
    }
}

// ---------------------------------------------------------------------------
// Launcher
// ---------------------------------------------------------------------------
extern "C" void kernel_launch(void* const* d_in, const int* in_sizes, int n_in,
                              void* d_out, int out_size)
{
    const float* obs     = (const float*)d_in[0];
    const float* actions = (const float*)d_in[1];
    const float* W1      = (const float*)d_in[2];
    const float* b1      = (const float*)d_in[3];
    const float* W2      = (const float*)d_in[4];
    const float* b2      = (const float*)d_in[5];
    const float* Wp1     = (const float*)d_in[6];
    const float* bp1     = (const float*)d_in[7];
    const float* Wp2     = (const float*)d_in[8];
    const float* bp2     = (const float*)d_in[9];
    const float* Ws1     = (const float*)d_in[10];
    const float* bs1     = (const float*)d_in[11];
    const float* Ws2     = (const float*)d_in[12];
    const float* bs2     = (const float*)d_in[13];
    const float* Ws3     = (const float*)d_in[14];
    const float* bs3     = (const float*)d_in[15];
    const float* Wg1     = (const float*)d_in[16];
    const float* bg1     = (const float*)d_in[17];
    const float* Wg2     = (const float*)d_in[18];
    const float* bg2     = (const float*)d_in[19];
    const float* Wg3     = (const float*)d_in[20];
    const float* bg3     = (const float*)d_in[21];
    const float* Wgate   = (const float*)d_in[22];
    const float* bgate   = (const float*)d_in[23];

    uint16_t *obsH, *obsL, *S1H, *S1L, *T1H, *T1L, *HH, *HL, *Wh, *Wl;
    float *PS, *SG;
    cudaGetSymbolAddress((void**)&obsH, g_obsH);
    cudaGetSymbolAddress((void**)&obsL, g_obsL);
    cudaGetSymbolAddress((void**)&S1H, g_S1H);
    cudaGetSymbolAddress((void**)&S1L, g_S1L);
    cudaGetSymbolAddress((void**)&T1H, g_T1H);
    cudaGetSymbolAddress((void**)&T1L, g_T1L);
    cudaGetSymbolAddress((void**)&HH, g_HH);
    cudaGetSymbolAddress((void**)&HL, g_HL);
    cudaGetSymbolAddress((void**)&Wh, g_Wh);
    cudaGetSymbolAddress((void**)&Wl, g_Wl);
    cudaGetSymbolAddress((void**)&PS, g_PS);
    cudaGetSymbolAddress((void**)&SG, g_SG);

    cudaFuncSetAttribute(gemm_tc2, cudaFuncAttributeMaxDynamicSharedMemorySize, SM_TOTAL);

    // ---- prep ----
    WPack wp;
    wp.d[0] = {W1,  512, 512, O_W1,  256 * 512};
    wp.d[1] = {W2,  256, 256, O_W2,  512 * 256};
    wp.d[2] = {Wp1, 256, 256, O_Wp1, 8 * 256 * 256};   // contiguous heads
    wp.d[3] = {Wp2, 40,  64,  O_Wp2, 0};               // handled specially below
    wp.d[4] = {Ws1, 512, 512, O_Ws1, 256 * 512};
    wp.d[5] = {Ws2, 256, 256, O_Ws2, 512 * 256};
    wp.d[6] = {Ws3, 128, 128, O_Ws3, 256 * 128};
    wp.d[7] = {Wg1, 512, 512, O_Wg1, 128 * 512};
    wp.d[8] = {Wg2, 256, 256, O_Wg2, 512 * 256};
    wp.d[9] = {Wg3, 128, 128, O_Wg3, 256 * 128};
    // Wp2: per-head 256x40 -> padded 256x64; treat as 8 separate K=2048 rows?
    // Simpler: K dimension concatenated: 8*256 rows of N=40 -> Np=64 each row.
    wp.d[3] = {Wp2, 40, 64, O_Wp2, 8 * 256 * 64};
    prep_weights<<<512, 256>>>(wp);
    size_t n4 = (size_t)BB * 384 / 4;
    prep_obs<<<(unsigned)((n4 + 255) / 256), 256>>>(obs, n4);

    dim3 blk(256);
    auto G = [](int Np) { return dim3((unsigned)(Np / 64), BB / 128); };

    // trunk
    gemm_tc2<<<G(512), blk, SM_TOTAL>>>(obsH, obsL, 384, Wh + O_W1, Wl + O_W1, 512,
        b1, 512, nullptr, S1H, S1L, 512, 256, 1, 1);
    gemm_tc2<<<G(256), blk, SM_TOTAL>>>(S1H, S1L, 512, Wh + O_W2, Wl + O_W2, 256,
        b2, 256, nullptr, T1H, T1L, 256, 512, 1, 1);

    // primitive heads
    for (int p = 0; p < 8; p++) {
        gemm_tc2<<<G(256), blk, SM_TOTAL>>>(T1H, T1L, 256,
            Wh + O_Wp1 + (size_t)p * 65536, Wl + O_Wp1 + (size_t)p * 65536, 256,
            bp1 + (size_t)p * 256, 256, nullptr,
            HH + (size_t)p * BB * 256, HL + (size_t)p * BB * 256, 256, 256, 1, 1);
    }
    for (int p = 0; p < 8; p++) {
        gemm_tc2<<<G(64), blk, SM_TOTAL>>>(HH + (size_t)p * BB * 256,
            HL + (size_t)p * BB * 256, 256,
            Wh + O_Wp2 + (size_t)p * 16384, Wl + O_Wp2 + (size_t)p * 16384, 64,
            bp2 + (size_t)p * 40, 40,
            PS + (size_t)p * BB * 40, nullptr, nullptr, 40, 256, 0, 0);
    }

    // gating branch (stat)
    gemm_tc2<<<G(512), blk, SM_TOTAL>>>(obsH, obsL, 384, Wh + O_Ws1, Wl + O_Ws1, 512,
        bs1, 512, nullptr, S1H, S1L, 512, 256, 1, 1);
    gemm_tc2<<<G(256), blk, SM_TOTAL>>>(S1H, S1L, 512, Wh + O_Ws2, Wl + O_Ws2, 256,
        bs2, 256, nullptr, T1H, T1L, 256, 512, 1, 1);
    gemm_tc2<<<G(128), blk, SM_TOTAL>>>(T1H, T1L, 256, Wh + O_Ws3, Wl + O_Ws3, 128,
        bs3, 128, SG, nullptr, nullptr, 256, 256, 0, 0);

    // gating branch (goal)
    gemm_tc2<<<G(512), blk, SM_TOTAL>>>(obsH + 256, obsL + 256, 384,
        Wh + O_Wg1, Wl + O_Wg1, 512,
        bg1, 512, nullptr, S1H, S1L, 512, 128, 1, 1);
    gemm_tc2<<<G(256), blk, SM_TOTAL>>>(S1H, S1L, 512, Wh + O_Wg2, Wl + O_Wg2, 256,
        bg2, 256, nullptr, T1H, T1L, 256, 512, 1, 1);
    gemm_tc2<<<G(128), blk, SM_TOTAL>>>(T1H, T1L, 256, Wh + O_Wg3, Wl + O_Wg3, 128,
        bg3, 128, SG + 128, nullptr, nullptr, 256, 256, 0, 0);

    // finalize
    finalize_kernel<<<BB / 8, blk>>>(SG, PS, actions, Wgate, bgate, (float*)d_out);
}

// round 7
// speedup vs baseline: 2.2835x; 1.1927x over previous
#include <cuda_runtime.h>
#include <cuda_bf16.h>
#include <cstdint>

// ---------------------------------------------------------------------------
#define BB 65536
static constexpr float LRELU = 0.01f;
static constexpr float LOG_SQRT_2PI_C = 0.91893853320467274178f;

// ---------------------------------------------------------------------------
// Device scratch
// ---------------------------------------------------------------------------
__device__ uint16_t g_obsH[(size_t)BB * 384];
__device__ uint16_t g_obsL[(size_t)BB * 384];
__device__ uint16_t g_S1H[(size_t)BB * 1024];   // [W1|Ws1] outputs
__device__ uint16_t g_S1L[(size_t)BB * 1024];
__device__ uint16_t g_G1H[(size_t)BB * 512];
__device__ uint16_t g_G1L[(size_t)BB * 512];
__device__ uint16_t g_T1H[(size_t)BB * 256];    // trunk2 out
__device__ uint16_t g_T1L[(size_t)BB * 256];
__device__ uint16_t g_T2H[(size_t)BB * 256];    // stat2 out
__device__ uint16_t g_T2L[(size_t)BB * 256];
__device__ uint16_t g_T3H[(size_t)BB * 256];    // goal2 out
__device__ uint16_t g_T3L[(size_t)BB * 256];
__device__ uint16_t g_HH[(size_t)BB * 2048];    // 8 heads concat on N
__device__ uint16_t g_HL[(size_t)BB * 2048];
__device__ float g_PS[(size_t)8 * BB * 40];
__device__ float g_SG[(size_t)BB * 256];
__device__ float g_bcat[1024];

static constexpr size_t WPOOL = 1441792;
__device__ uint16_t g_Wh[WPOOL];
__device__ uint16_t g_Wl[WPOOL];

// weight pool offsets
static constexpr size_t O_W1s = 0;         // 256 x 1024  ([W1|Ws1])
static constexpr size_t O_Wg1 = 262144;    // 128 x 512
static constexpr size_t O_W2  = 327680;    // 512 x 256
static constexpr size_t O_Ws2 = 458752;    // 512 x 256
static constexpr size_t O_Wg2 = 589824;    // 512 x 256
static constexpr size_t O_Ws3 = 720896;    // 256 x 128
static constexpr size_t O_Wg3 = 753664;    // 256 x 128
static constexpr size_t O_Wp1 = 786432;    // 256 x 2048 (heads on N)
static constexpr size_t O_Wp2 = 1310720;   // 8 x (256 x 64 pad)

// ---------------------------------------------------------------------------
// PTX helpers
// ---------------------------------------------------------------------------
__device__ __forceinline__ uint32_t smem_u32(const void* p) {
    uint32_t a;
    asm("{ .reg .u64 t; cvta.to.shared.u64 t, %1; cvt.u32.u64 %0, t; }"
        : "=r"(a) : "l"(p));
    return a;
}
__device__ __forceinline__ void cpa16(uint32_t dst, const void* src) {
    asm volatile("cp.async.cg.shared.global [%0], [%1], 16;"
                 :: "r"(dst), "l"(src) : "memory");
}
__device__ __forceinline__ void cp_commit() {
    asm volatile("cp.async.commit_group;" ::: "memory");
}
template <int N> __device__ __forceinline__ void cp_wait() {
    asm volatile("cp.async.wait_group %0;" :: "n"(N) : "memory");
}
__device__ __forceinline__ void ldsm4(uint32_t* r, uint32_t addr) {
    asm volatile("ldmatrix.sync.aligned.m8n8.x4.shared.b16 {%0,%1,%2,%3}, [%4];"
                 : "=r"(r[0]), "=r"(r[1]), "=r"(r[2]), "=r"(r[3]) : "r"(addr));
}
__device__ __forceinline__ void ldsm4t(uint32_t* r, uint32_t addr) {
    asm volatile("ldmatrix.sync.aligned.m8n8.x4.trans.shared.b16 {%0,%1,%2,%3}, [%4];"
                 : "=r"(r[0]), "=r"(r[1]), "=r"(r[2]), "=r"(r[3]) : "r"(addr));
}
__device__ __forceinline__ void mma_bf16(float* d, const uint32_t* a, const uint32_t* b) {
    asm volatile(
        "mma.sync.aligned.m16n8k16.row.col.f32.bf16.bf16.f32 "
        "{%0,%1,%2,%3}, {%4,%5,%6,%7}, {%8,%9}, {%0,%1,%2,%3};"
        : "+f"(d[0]), "+f"(d[1]), "+f"(d[2]), "+f"(d[3])
        : "r"(a[0]), "r"(a[1]), "r"(a[2]), "r"(a[3]), "r"(b[0]), "r"(b[1]));
}
__device__ __forceinline__ uint32_t pack_bf2(float a, float b) {
    __nv_bfloat162 h = __floats2bfloat162_rn(a, b);
    return *reinterpret_cast<uint32_t*>(&h);
}
__device__ __forceinline__ uint16_t bfh(float v) {
    __nv_bfloat16 h = __float2bfloat16_rn(v);
    return *reinterpret_cast<uint16_t*>(&h);
}
__device__ __forceinline__ float bff(uint16_t u) {
    __nv_bfloat16 h = *reinterpret_cast<__nv_bfloat16*>(&u);
    return __bfloat162float(h);
}

// ---------------------------------------------------------------------------
// Prep: split fp32 -> bf16 hi/lo planes with flexible dst layout
// ---------------------------------------------------------------------------
struct WDesc { const float* src; int N, Np, ldn; size_t off; int tot; };
struct WPack { WDesc d[24]; int cnt; };

__global__ void prep_weights(WPack p) {
    for (int e = 0; e < p.cnt; e++) {
        const WDesc w = p.d[e];
        for (int i = blockIdx.x * blockDim.x + threadIdx.x; i < w.tot;
             i += gridDim.x * blockDim.x) {
            int k = i / w.Np, n = i % w.Np;
            float v = (n < w.N) ? w.src[(size_t)k * w.N + n] : 0.f;
            uint16_t h = bfh(v);
            size_t dst = w.off + (size_t)k * w.ldn + n;
            g_Wh[dst] = h;
            g_Wl[dst] = bfh(v - bff(h));
        }
    }
}

__global__ void prep_obs(const float* __restrict__ src, size_t n4) {
    size_t i = (size_t)blockIdx.x * blockDim.x + threadIdx.x;
    if (i >= n4) return;
    float4 v = ((const float4*)src)[i];
    float h0 = bff(bfh(v.x)), h1 = bff(bfh(v.y));
    float h2 = bff(bfh(v.z)), h3 = bff(bfh(v.w));
    uint32_t* dh = (uint32_t*)&g_obsH[i * 4];
    uint32_t* dl = (uint32_t*)&g_obsL[i * 4];
    dh[0] = pack_bf2(h0, h1); dh[1] = pack_bf2(h2, h3);
    dl[0] = pack_bf2(v.x - h0, v.y - h1); dl[1] = pack_bf2(v.z - h2, v.w - h3);
}

__global__ void prep_bias(const float* __restrict__ b1, const float* __restrict__ bs1) {
    int i = blockIdx.x * blockDim.x + threadIdx.x;
    if (i < 512) g_bcat[i] = b1[i];
    else if (i < 1024) g_bcat[i] = bs1[i - 512];
}

// ---------------------------------------------------------------------------
// Split-bf16 GEMM, CTA tile 128 x NT, warp tile 32 x NT/2, K-chunk 32,
// 3-stage cp.async ring. mode 0: fp32 out; mode 1: split bf16 planes out.
// blockIdx.z batching via element strides.
// ---------------------------------------------------------------------------
template <int NT>
__global__ void __launch_bounds__(256) gemm_tc3(
    const uint16_t* __restrict__ Ah, const uint16_t* __restrict__ Al, int lda,
    const uint16_t* __restrict__ Bh, const uint16_t* __restrict__ Bl, int ldb,
    const float* __restrict__ bias, int Nreal,
    float* __restrict__ Cf, uint16_t* __restrict__ Chi, uint16_t* __restrict__ Clo,
    int ldc, int K, int act, int mode,
    size_t strideAz, size_t strideBz, size_t strideCz, int biasStride)
{
    constexpr int WN   = NT / 2;       // warp n-tile
    constexpr int NI   = WN / 8;       // n8 tiles per warp
    constexpr int BST  = NT + 8;       // B smem stride (halves)
    constexpr int SM_AL = 10240;       // A plane = 128*40*2
    constexpr int SM_BH = 20480;
    constexpr int SM_BL = 20480 + 32 * BST * 2;
    constexpr int STAGE = 20480 + 2 * 32 * BST * 2;
    constexpr int S = 3;

    extern __shared__ __align__(16) char smem[];
    const uint32_t sb = smem_u32(smem);

    const int t    = threadIdx.x;
    const int lane = t & 31;
    const int wid  = t >> 5;
    const int wm   = wid & 3;
    const int wn   = wid >> 2;
    const int m0   = blockIdx.y * 128;
    const int n0   = blockIdx.x * NT;
    const int z    = blockIdx.z;

    const uint16_t* Abase_h = Ah + (size_t)z * strideAz;
    const uint16_t* Abase_l = Al + (size_t)z * strideAz;
    const uint16_t* Bbase_h = Bh + (size_t)z * strideBz;
    const uint16_t* Bbase_l = Bl + (size_t)z * strideBz;
    const float*    biasp   = bias + (size_t)z * biasStride;

    auto issue = [&](int c, int buf) {
        const uint32_t base = sb + buf * STAGE;
        const int k0 = c << 5;
        // A: 512 segs/plane, 2 per thread per plane
#pragma unroll
        for (int j = 0; j < 2; j++) {
            int i = t + 256 * j;
            int ar = i >> 2, as = i & 3;
            uint32_t off = (ar * 40 + as * 8) * 2;
            const uint16_t* sh = Abase_h + (size_t)(m0 + ar) * lda + k0 + as * 8;
            const uint16_t* sl = Abase_l + (size_t)(m0 + ar) * lda + k0 + as * 8;
            cpa16(base + off, sh);
            cpa16(base + SM_AL + off, sl);
        }
        // B: 32*NT/8 segs/plane
#pragma unroll
        for (int j = 0; j < NT / 64; j++) {
            int i = t + 256 * j;
            int br = i / (NT / 8), bs = i % (NT / 8);
            uint32_t off = (br * BST + bs * 8) * 2;
            const uint16_t* sh = Bbase_h + (size_t)(k0 + br) * ldb + n0 + bs * 8;
            const uint16_t* sl = Bbase_l + (size_t)(k0 + br) * ldb + n0 + bs * 8;
            cpa16(base + SM_BH + off, sh);
            cpa16(base + SM_BL + off, sl);
        }
    };

    float acc[2][NI][4];
#pragma unroll
    for (int i = 0; i < 2; i++)
#pragma unroll
        for (int j = 0; j < NI; j++)
#pragma unroll
            for (int q = 0; q < 4; q++) acc[i][j][q] = 0.f;

    const int nch = K >> 5;
    for (int s = 0; s < S - 1 && s < nch; s++) { issue(s, s % S); cp_commit(); }

    for (int c = 0; c < nch; c++) {
        if (c + S - 1 < nch) issue(c + S - 1, (c + S - 1) % S);
        cp_commit();
        cp_wait<S - 1>();
        __syncthreads();

        const uint32_t base = sb + (c % S) * STAGE;
#pragma unroll
        for (int ks = 0; ks < 32; ks += 16) {
            uint32_t Afh[2][4], Afl[2][4], Bfh[NI][2], Bfl[NI][2];
            {
                int r  = lane & 15;
                int kq = (lane >> 4) * 8;
#pragma unroll
                for (int mi = 0; mi < 2; mi++) {
                    int m = wm * 32 + mi * 16 + r;
                    uint32_t off = (m * 40 + ks + kq) * 2;
                    ldsm4(Afh[mi], base + off);
                    ldsm4(Afl[mi], base + SM_AL + off);
                }
            }
            {
                int g  = lane >> 3;
                int rr = lane & 7;
                int krow = ks + (g & 1) * 8 + rr;
                int ncol = (g >> 1) * 8;
#pragma unroll
                for (int blk = 0; blk < NI / 2; blk++) {
                    int nb = wn * WN + blk * 16 + ncol;
                    uint32_t off = (krow * BST + nb) * 2;
                    ldsm4t(&Bfh[blk * 2][0], base + SM_BH + off);
                    ldsm4t(&Bfl[blk * 2][0], base + SM_BL + off);
                }
            }
#pragma unroll
            for (int mi = 0; mi < 2; mi++)
#pragma unroll
                for (int ni = 0; ni < NI; ni++) {
                    mma_bf16(acc[mi][ni], Afh[mi], Bfh[ni]);
                    mma_bf16(acc[mi][ni], Afh[mi], Bfl[ni]);
                    mma_bf16(acc[mi][ni], Afl[mi], Bfh[ni]);
                }
        }
        __syncthreads();
    }

    // ---- epilogue ----
    const int r4 = lane >> 2;
    const int c2 = (lane & 3) * 2;
#pragma unroll
    for (int mi = 0; mi < 2; mi++) {
#pragma unroll
        for (int ni = 0; ni < NI; ni++) {
            int col = n0 + wn * WN + ni * 8 + c2;
            int row = m0 + wm * 32 + mi * 16 + r4;
            if (mode == 0 && col >= Nreal) continue;
            float b0 = biasp[col], b1 = biasp[col + 1];
            float v0 = acc[mi][ni][0] + b0;
            float v1 = acc[mi][ni][1] + b1;
            float v2 = acc[mi][ni][2] + b0;
            float v3 = acc[mi][ni][3] + b1;
            if (act) {
                v0 = v0 > 0.f ? v0 : LRELU * v0;
                v1 = v1 > 0.f ? v1 : LRELU * v1;
                v2 = v2 > 0.f ? v2 : LRELU * v2;
                v3 = v3 > 0.f ? v3 : LRELU * v3;
            }
            size_t i0 = (size_t)z * strideCz + (size_t)row * ldc + col;
            size_t i1 = (size_t)z * strideCz + (size_t)(row + 8) * ldc + col;
            if (mode == 0) {
                *(float2*)&Cf[i0] = make_float2(v0, v1);
                *(float2*)&Cf[i1] = make_float2(v2, v3);
            } else {
                float h0 = bff(bfh(v0)), h1 = bff(bfh(v1));
                float h2 = bff(bfh(v2)), h3 = bff(bfh(v3));
                *(uint32_t*)&Chi[i0] = pack_bf2(h0, h1);
                *(uint32_t*)&Clo[i0] = pack_bf2(v0 - h0, v1 - h1);
                *(uint32_t*)&Chi[i1] = pack_bf2(h2, h3);
                *(uint32_t*)&Clo[i1] = pack_bf2(v2 - h2, v3 - h3);
            }
        }
    }
}

// ---------------------------------------------------------------------------
// Finalize
// ---------------------------------------------------------------------------
__global__ __launch_bounds__(256) void finalize_kernel(
    const float* __restrict__ SG, const float* __restrict__ PS,
    const float* __restrict__ actions,
    const float* __restrict__ Wgate, const float* __restrict__ bgate,
    float* __restrict__ out)
{
    __shared__ float Wg_s[8 * 256];
    const int t = threadIdx.x;
    for (int i = t; i < 2048; i += 256) {
        int k = i >> 3, p = i & 7;
        Wg_s[p * 256 + k] = Wgate[i];
    }
    __syncthreads();

    const int warp = t >> 5, lane = t & 31;
    const size_t row = (size_t)blockIdx.x * 8 + warp;

    float accp[8] = {0, 0, 0, 0, 0, 0, 0, 0};
#pragma unroll
    for (int i = 0; i < 8; i++) {
        float v = SG[row * 256 + lane + 32 * i];
        v = v > 0.f ? v : LRELU * v;
#pragma unroll
        for (int p = 0; p < 8; p++)
            accp[p] += v * Wg_s[p * 256 + lane + 32 * i];
    }
#pragma unroll
    for (int off = 16; off; off >>= 1)
#pragma unroll
        for (int p = 0; p < 8; p++)
            accp[p] += __shfl_xor_sync(0xffffffffu, accp[p], off);

    float wg[8];
#pragma unroll
    for (int p = 0; p < 8; p++)
        wg[p] = expf(accp[p] + bgate[p]);

    float lp = 0.f, ent = 0.f;
    if (lane < 20) {
        float s1 = 0.f, s2 = 0.f;
#pragma unroll
        for (int p = 0; p < 8; p++) {
            const float* psr = PS + ((size_t)p * BB + row) * 40;
            float mu = psr[lane];
            float lg = psr[20 + lane];
            float inv = wg[p] * expf(-lg);
            s1 += mu * inv;
            s2 += inv;
        }
        float a = actions[row * 20 + lane];
        float z = (a - s1 / s2) * s2;
        float logsig = -logf(s2);
        lp  = -0.5f * z * z - logsig - LOG_SQRT_2PI_C;
        ent = 0.5f + LOG_SQRT_2PI_C + logsig;
    }
#pragma unroll
    for (int off = 16; off; off >>= 1) {
        lp  += __shfl_xor_sync(0xffffffffu, lp,  off);
        ent += __shfl_xor_sync(0xffffffffu, ent, off);
    }
    if (lane == 0) {
        out[row * 2]     = lp;
        out[row * 2 + 1] = ent;
    }
}

// ---------------------------------------------------------------------------
// Launcher
// ---------------------------------------------------------------------------
static constexpr int SMEM128 = 3 * (20480 + 2 * 32 * 136 * 2);  // 113664
static constexpr int SMEM64  = 3 * (20480 + 2 * 32 * 72 * 2);   // 89088

extern "C" void kernel_launch(void* const* d_in, const int* in_sizes, int n_in,
                              void* d_out, int out_size)
{
    const float* obs     = (const float*)d_in[0];
    const float* actions = (const float*)d_in[1];
    const float* W1      = (const float*)d_in[2];
    const float* b1      = (const float*)d_in[3];
    const float* W2      = (const float*)d_in[4];
    const float* b2      = (const float*)d_in[5];
    const float* Wp1     = (const float*)d_in[6];
    const float* bp1     = (const float*)d_in[7];
    const float* Wp2     = (const float*)d_in[8];
    const float* bp2     = (const float*)d_in[9];
    const float* Ws1     = (const float*)d_in[10];
    const float* bs1     = (const float*)d_in[11];
    const float* Ws2     = (const float*)d_in[12];
    const float* bs2     = (const float*)d_in[13];
    const float* Ws3     = (const float*)d_in[14];
    const float* bs3     = (const float*)d_in[15];
    const float* Wg1     = (const float*)d_in[16];
    const float* bg1     = (const float*)d_in[17];
    const float* Wg2     = (const float*)d_in[18];
    const float* bg2     = (const float*)d_in[19];
    const float* Wg3     = (const float*)d_in[20];
    const float* bg3     = (const float*)d_in[21];
    const float* Wgate   = (const float*)d_in[22];
    const float* bgate   = (const float*)d_in[23];

    uint16_t *obsH, *obsL, *S1H, *S1L, *G1H, *G1L;
    uint16_t *T1H, *T1L, *T2H, *T2L, *T3H, *T3L, *HH, *HL, *Wh, *Wl;
    float *PS, *SG, *bcat;
    cudaGetSymbolAddress((void**)&obsH, g_obsH);
    cudaGetSymbolAddress((void**)&obsL, g_obsL);
    cudaGetSymbolAddress((void**)&S1H, g_S1H);
    cudaGetSymbolAddress((void**)&S1L, g_S1L);
    cudaGetSymbolAddress((void**)&G1H, g_G1H);
    cudaGetSymbolAddress((void**)&G1L, g_G1L);
    cudaGetSymbolAddress((void**)&T1H, g_T1H);
    cudaGetSymbolAddress((void**)&T1L, g_T1L);
    cudaGetSymbolAddress((void**)&T2H, g_T2H);
    cudaGetSymbolAddress((void**)&T2L, g_T2L);
    cudaGetSymbolAddress((void**)&T3H, g_T3H);
    cudaGetSymbolAddress((void**)&T3L, g_T3L);
    cudaGetSymbolAddress((void**)&HH, g_HH);
    cudaGetSymbolAddress((void**)&HL, g_HL);
    cudaGetSymbolAddress((void**)&Wh, g_Wh);
    cudaGetSymbolAddress((void**)&Wl, g_Wl);
    cudaGetSymbolAddress((void**)&PS, g_PS);
    cudaGetSymbolAddress((void**)&SG, g_SG);
    cudaGetSymbolAddress((void**)&bcat, g_bcat);

    cudaFuncSetAttribute(gemm_tc3<128>, cudaFuncAttributeMaxDynamicSharedMemorySize, SMEM128);
    cudaFuncSetAttribute(gemm_tc3<64>,  cudaFuncAttributeMaxDynamicSharedMemorySize, SMEM64);

    // ---- prep ----
    WPack wp{};
    int e = 0;
    wp.d[e++] = {W1,  512, 512, 1024, O_W1s,       256 * 512};
    wp.d[e++] = {Ws1, 512, 512, 1024, O_W1s + 512, 256 * 512};
    wp.d[e++] = {Wg1, 512, 512, 512,  O_Wg1, 128 * 512};
    wp.d[e++] = {W2,  256, 256, 256,  O_W2,  512 * 256};
    wp.d[e++] = {Ws2, 256, 256, 256,  O_Ws2, 512 * 256};
    wp.d[e++] = {Wg2, 256, 256, 256,  O_Wg2, 512 * 256};
    wp.d[e++] = {Ws3, 128, 128, 128,  O_Ws3, 256 * 128};
    wp.d[e++] = {Wg3, 128, 128, 128,  O_Wg3, 256 * 128};
    for (int p = 0; p < 8; p++)
        wp.d[e++] = {Wp1 + (size_t)p * 65536, 256, 256, 2048,
                     O_Wp1 + (size_t)p * 256, 256 * 256};
    for (int p = 0; p < 8; p++)
        wp.d[e++] = {Wp2 + (size_t)p * 10240, 40, 64, 64,
                     O_Wp2 + (size_t)p * 16384, 256 * 64};
    wp.cnt = e;
    prep_weights<<<512, 256>>>(wp);
    size_t n4 = (size_t)BB * 384 / 4;
    prep_obs<<<(unsigned)((n4 + 255) / 256), 256>>>(obs, n4);
    prep_bias<<<4, 256>>>(b1, bs1);

    dim3 blk(256);

    // 1. [W1|Ws1]: obs_stat (K=256) -> S1 (N=1024)
    gemm_tc3<128><<<dim3(8, 512), blk, SMEM128>>>(obsH, obsL, 384,
        Wh + O_W1s, Wl + O_W1s, 1024, bcat, 1024,
        nullptr, S1H, S1L, 1024, 256, 1, 1, 0, 0, 0, 0);
    // 2. Wg1: obs_goal (K=128) -> G1 (N=512)
    gemm_tc3<128><<<dim3(4, 512), blk, SMEM128>>>(obsH + 256, obsL + 256, 384,
        Wh + O_Wg1, Wl + O_Wg1, 512, bg1, 512,
        nullptr, G1H, G1L, 512, 128, 1, 1, 0, 0, 0, 0);
    // 3. trunk2: S1[:,0:512] -> T1 (N=256)
    gemm_tc3<128><<<dim3(2, 512), blk, SMEM128>>>(S1H, S1L, 1024,
        Wh + O_W2, Wl + O_W2, 256, b2, 256,
        nullptr, T1H, T1L, 256, 512, 1, 1, 0, 0, 0, 0);
    // 4. stat2: S1[:,512:1024] -> T2 (N=256)
    gemm_tc3<128><<<dim3(2, 512), blk, SMEM128>>>(S1H + 512, S1L + 512, 1024,
        Wh + O_Ws2, Wl + O_Ws2, 256, bs2, 256,
        nullptr, T2H, T2L, 256, 512, 1, 1, 0, 0, 0, 0);
    // 5. goal2: G1 -> T3 (N=256)
    gemm_tc3<128><<<dim3(2, 512), blk, SMEM128>>>(G1H, G1L, 512,
        Wh + O_Wg2, Wl + O_Wg2, 256, bg2, 256,
        nullptr, T3H, T3L, 256, 512, 1, 1, 0, 0, 0, 0);
    // 6. Ws3: T2 -> SG[:,0:128] (fp32)
    gemm_tc3<128><<<dim3(1, 512), blk, SMEM128>>>(T2H, T2L, 256,
        Wh + O_Ws3, Wl + O_Ws3, 128, bs3, 128,
        SG, nullptr, nullptr, 256, 256, 0, 0, 0, 0, 0, 0);
    // 7. Wg3: T3 -> SG[:,128:256] (fp32)
    gemm_tc3<128><<<dim3(1, 512), blk, SMEM128>>>(T3H, T3L, 256,
        Wh + O_Wg3, Wl + O_Wg3, 128, bg3, 128,
        SG + 128, nullptr, nullptr, 256, 256, 0, 0, 0, 0, 0, 0);
    // 8. Wp1 (8 heads concat on N): T1 -> H (N=2048)   bp1 is flat-concat bias
    gemm_tc3<128><<<dim3(16, 512), blk, SMEM128>>>(T1H, T1L, 256,
        Wh + O_Wp1, Wl + O_Wp1, 2048, bp1, 2048,
        nullptr, HH, HL, 2048, 256, 1, 1, 0, 0, 0, 0);
    // 9. Wp2 batched z=8: H[:, p*256:(p+1)*256] -> PS[p] (N=40, pad 64)
    gemm_tc3<64><<<dim3(1, 512, 8), blk, SMEM64>>>(HH, HL, 2048,
        Wh + O_Wp2, Wl + O_Wp2, 64, bp2, 40,
        PS, nullptr, nullptr, 40, 256, 0, 0,
        256, 16384, (size_t)BB * 40, 40);

    // finalize
    finalize_kernel<<<BB / 8, blk>>>(SG, PS, actions, Wgate, bgate, (float*)d_out);
}

// round 8
// speedup vs baseline: 2.3507x; 1.0294x over previous
#include <cuda_runtime.h>
#include <cuda_bf16.h>
#include <cstdint>

// ---------------------------------------------------------------------------
#define BB 65536
static constexpr float LRELU = 0.01f;
static constexpr float LOG_SQRT_2PI_C = 0.91893853320467274178f;

// ---------------------------------------------------------------------------
// Device scratch
// ---------------------------------------------------------------------------
__device__ uint16_t g_obsH[(size_t)BB * 384];
__device__ uint16_t g_obsL[(size_t)BB * 384];
__device__ uint16_t g_S1H[(size_t)BB * 1536];   // [W1|Ws1|Wg1] outputs
__device__ uint16_t g_S1L[(size_t)BB * 1536];
__device__ uint16_t g_T1H[(size_t)BB * 256];    // trunk2 out
__device__ uint16_t g_T1L[(size_t)BB * 256];
__device__ uint16_t g_T2H[(size_t)BB * 256];    // stat2 out
__device__ uint16_t g_T2L[(size_t)BB * 256];
__device__ uint16_t g_T3H[(size_t)BB * 256];    // goal2 out
__device__ uint16_t g_T3L[(size_t)BB * 256];
__device__ uint16_t g_HH[(size_t)BB * 2048];    // 8 heads concat on N
__device__ uint16_t g_HL[(size_t)BB * 2048];
__device__ float g_PS[(size_t)8 * BB * 40];
__device__ float g_SG[(size_t)BB * 256];
__device__ float g_bcat[1024];

static constexpr size_t WPOOL = 1441792;
__device__ uint16_t g_Wh[WPOOL];
__device__ uint16_t g_Wl[WPOOL];

// weight pool offsets
static constexpr size_t O_W1s = 0;         // 256 x 1024  ([W1|Ws1])
static constexpr size_t O_Wg1 = 262144;    // 128 x 512
static constexpr size_t O_W2  = 327680;    // 512 x 256
static constexpr size_t O_Ws2 = 458752;    // 512 x 256
static constexpr size_t O_Wg2 = 589824;    // 512 x 256
static constexpr size_t O_Ws3 = 720896;    // 256 x 128
static constexpr size_t O_Wg3 = 753664;    // 256 x 128
static constexpr size_t O_Wp1 = 786432;    // 256 x 2048 (heads on N)
static constexpr size_t O_Wp2 = 1310720;   // 8 x (256 x 64 pad)

// ---------------------------------------------------------------------------
// PTX helpers
// ---------------------------------------------------------------------------
__device__ __forceinline__ uint32_t smem_u32(const void* p) {
    uint32_t a;
    asm("{ .reg .u64 t; cvta.to.shared.u64 t, %1; cvt.u32.u64 %0, t; }"
        : "=r"(a) : "l"(p));
    return a;
}
__device__ __forceinline__ void cpa16(uint32_t dst, const void* src) {
    asm volatile("cp.async.cg.shared.global [%0], [%1], 16;"
                 :: "r"(dst), "l"(src) : "memory");
}
__device__ __forceinline__ void cp_commit() {
    asm volatile("cp.async.commit_group;" ::: "memory");
}
template <int N> __device__ __forceinline__ void cp_wait() {
    asm volatile("cp.async.wait_group %0;" :: "n"(N) : "memory");
}
__device__ __forceinline__ void ldsm4(uint32_t* r, uint32_t addr) {
    asm volatile("ldmatrix.sync.aligned.m8n8.x4.shared.b16 {%0,%1,%2,%3}, [%4];"
                 : "=r"(r[0]), "=r"(r[1]), "=r"(r[2]), "=r"(r[3]) : "r"(addr));
}
__device__ __forceinline__ void ldsm4t(uint32_t* r, uint32_t addr) {
    asm volatile("ldmatrix.sync.aligned.m8n8.x4.trans.shared.b16 {%0,%1,%2,%3}, [%4];"
                 : "=r"(r[0]), "=r"(r[1]), "=r"(r[2]), "=r"(r[3]) : "r"(addr));
}
__device__ __forceinline__ void mma_bf16(float* d, const uint32_t* a, const uint32_t* b) {
    asm volatile(
        "mma.sync.aligned.m16n8k16.row.col.f32.bf16.bf16.f32 "
        "{%0,%1,%2,%3}, {%4,%5,%6,%7}, {%8,%9}, {%0,%1,%2,%3};"
        : "+f"(d[0]), "+f"(d[1]), "+f"(d[2]), "+f"(d[3])
        : "r"(a[0]), "r"(a[1]), "r"(a[2]), "r"(a[3]), "r"(b[0]), "r"(b[1]));
}
__device__ __forceinline__ uint32_t pack_bf2(float a, float b) {
    __nv_bfloat162 h = __floats2bfloat162_rn(a, b);
    return *reinterpret_cast<uint32_t*>(&h);
}
__device__ __forceinline__ uint16_t bfh(float v) {
    __nv_bfloat16 h = __float2bfloat16_rn(v);
    return *reinterpret_cast<uint16_t*>(&h);
}
__device__ __forceinline__ float bff(uint16_t u) {
    __nv_bfloat16 h = *reinterpret_cast<__nv_bfloat16*>(&u);
    return __bfloat162float(h);
}

// ---------------------------------------------------------------------------
// Prep: split fp32 -> bf16 hi/lo planes with flexible dst layout
// ---------------------------------------------------------------------------
struct WDesc { const float* src; int N, Np, ldn; size_t off; int tot; };
struct WPack { WDesc d[24]; int cnt; };

__global__ void prep_weights(WPack p) {
    for (int e = 0; e < p.cnt; e++) {
        const WDesc w = p.d[e];
        for (int i = blockIdx.x * blockDim.x + threadIdx.x; i < w.tot;
             i += gridDim.x * blockDim.x) {
            int k = i / w.Np, n = i % w.Np;
            float v = (n < w.N) ? w.src[(size_t)k * w.N + n] : 0.f;
            uint16_t h = bfh(v);
            size_t dst = w.off + (size_t)k * w.ldn + n;
            g_Wh[dst] = h;
            g_Wl[dst] = bfh(v - bff(h));
        }
    }
}

__global__ void prep_obs(const float* __restrict__ src, size_t n4) {
    size_t i = (size_t)blockIdx.x * blockDim.x + threadIdx.x;
    if (i >= n4) return;
    float4 v = ((const float4*)src)[i];
    float h0 = bff(bfh(v.x)), h1 = bff(bfh(v.y));
    float h2 = bff(bfh(v.z)), h3 = bff(bfh(v.w));
    uint32_t* dh = (uint32_t*)&g_obsH[i * 4];
    uint32_t* dl = (uint32_t*)&g_obsL[i * 4];
    dh[0] = pack_bf2(h0, h1); dh[1] = pack_bf2(h2, h3);
    dl[0] = pack_bf2(v.x - h0, v.y - h1); dl[1] = pack_bf2(v.z - h2, v.w - h3);
}

__global__ void prep_bias(const float* __restrict__ b1, const float* __restrict__ bs1) {
    int i = blockIdx.x * blockDim.x + threadIdx.x;
    if (i < 512) g_bcat[i] = b1[i];
    else if (i < 1024) g_bcat[i] = bs1[i - 512];
}

// ---------------------------------------------------------------------------
// Split-bf16 GEMM, CTA tile 128 x NT, warp tile 32 x NT/2, K-chunk 32,
// 3-stage cp.async ring. mode 0: fp32 out; mode 1: split bf16 planes out.
// blockIdx.z batching via element strides.
// ---------------------------------------------------------------------------
template <int NT>
__global__ void __launch_bounds__(256) gemm_tc3(
    const uint16_t* __restrict__ Ah, const uint16_t* __restrict__ Al, int lda,
    const uint16_t* __restrict__ Bh, const uint16_t* __restrict__ Bl, int ldb,
    const float* __restrict__ bias, int Nreal,
    float* __restrict__ Cf, uint16_t* __restrict__ Chi, uint16_t* __restrict__ Clo,
    int ldc, int K, int act, int mode,
    size_t strideAz, size_t strideBz, size_t strideCz, int biasStride)
{
    constexpr int WN   = NT / 2;
    constexpr int NI   = WN / 8;
    constexpr int BST  = NT + 8;
    constexpr int SM_AL = 10240;
    constexpr int SM_BH = 20480;
    constexpr int SM_BL = 20480 + 32 * BST * 2;
    constexpr int STAGE = 20480 + 2 * 32 * BST * 2;
    constexpr int S = 3;

    extern __shared__ __align__(16) char smem[];
    const uint32_t sb = smem_u32(smem);

    const int t    = threadIdx.x;
    const int lane = t & 31;
    const int wid  = t >> 5;
    const int wm   = wid & 3;
    const int wn   = wid >> 2;
    const int m0   = blockIdx.y * 128;
    const int n0   = blockIdx.x * NT;
    const int z    = blockIdx.z;

    const uint16_t* Abase_h = Ah + (size_t)z * strideAz;
    const uint16_t* Abase_l = Al + (size_t)z * strideAz;
    const uint16_t* Bbase_h = Bh + (size_t)z * strideBz;
    const uint16_t* Bbase_l = Bl + (size_t)z * strideBz;
    const float*    biasp   = bias + (size_t)z * biasStride;

    auto issue = [&](int c, int buf) {
        const uint32_t base = sb + buf * STAGE;
        const int k0 = c << 5;
#pragma unroll
        for (int j = 0; j < 2; j++) {
            int i = t + 256 * j;
            int ar = i >> 2, as = i & 3;
            uint32_t off = (ar * 40 + as * 8) * 2;
            const uint16_t* sh = Abase_h + (size_t)(m0 + ar) * lda + k0 + as * 8;
            const uint16_t* sl = Abase_l + (size_t)(m0 + ar) * lda + k0 + as * 8;
            cpa16(base + off, sh);
            cpa16(base + SM_AL + off, sl);
        }
#pragma unroll
        for (int j = 0; j < NT / 64; j++) {
            int i = t + 256 * j;
            int br = i / (NT / 8), bs = i % (NT / 8);
            uint32_t off = (br * BST + bs * 8) * 2;
            const uint16_t* sh = Bbase_h + (size_t)(k0 + br) * ldb + n0 + bs * 8;
            const uint16_t* sl = Bbase_l + (size_t)(k0 + br) * ldb + n0 + bs * 8;
            cpa16(base + SM_BH + off, sh);
            cpa16(base + SM_BL + off, sl);
        }
    };

    float acc[2][NI][4];
#pragma unroll
    for (int i = 0; i < 2; i++)
#pragma unroll
        for (int j = 0; j < NI; j++)
#pragma unroll
            for (int q = 0; q < 4; q++) acc[i][j][q] = 0.f;

    const int nch = K >> 5;
    for (int s = 0; s < S - 1 && s < nch; s++) { issue(s, s % S); cp_commit(); }

    for (int c = 0; c < nch; c++) {
        if (c + S - 1 < nch) issue(c + S - 1, (c + S - 1) % S);
        cp_commit();
        cp_wait<S - 1>();
        __syncthreads();

        const uint32_t base = sb + (c % S) * STAGE;
#pragma unroll
        for (int ks = 0; ks < 32; ks += 16) {
            uint32_t Afh[2][4], Afl[2][4], Bfh[NI][2], Bfl[NI][2];
            {
                int r  = lane & 15;
                int kq = (lane >> 4) * 8;
#pragma unroll
                for (int mi = 0; mi < 2; mi++) {
                    int m = wm * 32 + mi * 16 + r;
                    uint32_t off = (m * 40 + ks + kq) * 2;
                    ldsm4(Afh[mi], base + off);
                    ldsm4(Afl[mi], base + SM_AL + off);
                }
            }
            {
                int g  = lane >> 3;
                int rr = lane & 7;
                int krow = ks + (g & 1) * 8 + rr;
                int ncol = (g >> 1) * 8;
#pragma unroll
                for (int blk = 0; blk < NI / 2; blk++) {
                    int nb = wn * WN + blk * 16 + ncol;
                    uint32_t off = (krow * BST + nb) * 2;
                    ldsm4t(&Bfh[blk * 2][0], base + SM_BH + off);
                    ldsm4t(&Bfl[blk * 2][0], base + SM_BL + off);
                }
            }
#pragma unroll
            for (int mi = 0; mi < 2; mi++)
#pragma unroll
                for (int ni = 0; ni < NI; ni++) {
                    mma_bf16(acc[mi][ni], Afh[mi], Bfh[ni]);
                    mma_bf16(acc[mi][ni], Afh[mi], Bfl[ni]);
                    mma_bf16(acc[mi][ni], Afl[mi], Bfh[ni]);
                }
        }
        __syncthreads();
    }

    // ---- epilogue ----
    const int r4 = lane >> 2;
    const int c2 = (lane & 3) * 2;
#pragma unroll
    for (int mi = 0; mi < 2; mi++) {
#pragma unroll
        for (int ni = 0; ni < NI; ni++) {
            int col = n0 + wn * WN + ni * 8 + c2;
            int row = m0 + wm * 32 + mi * 16 + r4;
            if (mode == 0 && col >= Nreal) continue;
            float b0 = biasp[col], b1 = biasp[col + 1];
            float v0 = acc[mi][ni][0] + b0;
            float v1 = acc[mi][ni][1] + b1;
            float v2 = acc[mi][ni][2] + b0;
            float v3 = acc[mi][ni][3] + b1;
            if (act) {
                v0 = v0 > 0.f ? v0 : LRELU * v0;
                v1 = v1 > 0.f ? v1 : LRELU * v1;
                v2 = v2 > 0.f ? v2 : LRELU * v2;
                v3 = v3 > 0.f ? v3 : LRELU * v3;
            }
            size_t i0 = (size_t)z * strideCz + (size_t)row * ldc + col;
            size_t i1 = (size_t)z * strideCz + (size_t)(row + 8) * ldc + col;
            if (mode == 0) {
                *(float2*)&Cf[i0] = make_float2(v0, v1);
                *(float2*)&Cf[i1] = make_float2(v2, v3);
            } else {
                float h0 = bff(bfh(v0)), h1 = bff(bfh(v1));
                float h2 = bff(bfh(v2)), h3 = bff(bfh(v3));
                *(uint32_t*)&Chi[i0] = pack_bf2(h0, h1);
                *(uint32_t*)&Clo[i0] = pack_bf2(v0 - h0, v1 - h1);
                *(uint32_t*)&Chi[i1] = pack_bf2(h2, h3);
                *(uint32_t*)&Clo[i1] = pack_bf2(v2 - h2, v3 - h3);
            }
        }
    }
}

// ---------------------------------------------------------------------------
// Finalize
// ---------------------------------------------------------------------------
__global__ __launch_bounds__(256) void finalize_kernel(
    const float* __restrict__ SG, const float* __restrict__ PS,
    const float* __restrict__ actions,
    const float* __restrict__ Wgate, const float* __restrict__ bgate,
    float* __restrict__ out)
{
    __shared__ float Wg_s[8 * 256];
    const int t = threadIdx.x;
    for (int i = t; i < 2048; i += 256) {
        int k = i >> 3, p = i & 7;
        Wg_s[p * 256 + k] = Wgate[i];
    }
    __syncthreads();

    const int warp = t >> 5, lane = t & 31;
    const size_t row = (size_t)blockIdx.x * 8 + warp;

    float accp[8] = {0, 0, 0, 0, 0, 0, 0, 0};
#pragma unroll
    for (int i = 0; i < 8; i++) {
        float v = SG[row * 256 + lane + 32 * i];
        v = v > 0.f ? v : LRELU * v;
#pragma unroll
        for (int p = 0; p < 8; p++)
            accp[p] += v * Wg_s[p * 256 + lane + 32 * i];
    }
#pragma unroll
    for (int off = 16; off; off >>= 1)
#pragma unroll
        for (int p = 0; p < 8; p++)
            accp[p] += __shfl_xor_sync(0xffffffffu, accp[p], off);

    float wg[8];
#pragma unroll
    for (int p = 0; p < 8; p++)
        wg[p] = expf(accp[p] + bgate[p]);

    float lp = 0.f, ent = 0.f;
    if (lane < 20) {
        float s1 = 0.f, s2 = 0.f;
#pragma unroll
        for (int p = 0; p < 8; p++) {
            const float* psr = PS + ((size_t)p * BB + row) * 40;
            float mu = psr[lane];
            float lg = psr[20 + lane];
            float inv = wg[p] * expf(-lg);
            s1 += mu * inv;
            s2 += inv;
        }
        float a = actions[row * 20 + lane];
        float z = (a - s1 / s2) * s2;
        float logsig = -logf(s2);
        lp  = -0.5f * z * z - logsig - LOG_SQRT_2PI_C;
        ent = 0.5f + LOG_SQRT_2PI_C + logsig;
    }
#pragma unroll
    for (int off = 16; off; off >>= 1) {
        lp  += __shfl_xor_sync(0xffffffffu, lp,  off);
        ent += __shfl_xor_sync(0xffffffffu, ent, off);
    }
    if (lane == 0) {
        out[row * 2]     = lp;
        out[row * 2 + 1] = ent;
    }
}

// ---------------------------------------------------------------------------
// Launcher with stream fork/join (graph-capturable DAG)
// ---------------------------------------------------------------------------
static constexpr int SMEM128 = 3 * (20480 + 2 * 32 * 136 * 2);  // 113664
static constexpr int SMEM64  = 3 * (20480 + 2 * 32 * 72 * 2);   // 89088

extern "C" void kernel_launch(void* const* d_in, const int* in_sizes, int n_in,
                              void* d_out, int out_size)
{
    const float* obs     = (const float*)d_in[0];
    const float* actions = (const float*)d_in[1];
    const float* W1      = (const float*)d_in[2];
    const float* b1      = (const float*)d_in[3];
    const float* W2      = (const float*)d_in[4];
    const float* b2      = (const float*)d_in[5];
    const float* Wp1     = (const float*)d_in[6];
    const float* bp1     = (const float*)d_in[7];
    const float* Wp2     = (const float*)d_in[8];
    const float* bp2     = (const float*)d_in[9];
    const float* Ws1     = (const float*)d_in[10];
    const float* bs1     = (const float*)d_in[11];
    const float* Ws2     = (const float*)d_in[12];
    const float* bs2     = (const float*)d_in[13];
    const float* Ws3     = (const float*)d_in[14];
    const float* bs3     = (const float*)d_in[15];
    const float* Wg1     = (const float*)d_in[16];
    const float* bg1     = (const float*)d_in[17];
    const float* Wg2     = (const float*)d_in[18];
    const float* bg2     = (const float*)d_in[19];
    const float* Wg3     = (const float*)d_in[20];
    const float* bg3     = (const float*)d_in[21];
    const float* Wgate   = (const float*)d_in[22];
    const float* bgate   = (const float*)d_in[23];

    uint16_t *obsH, *obsL, *S1H, *S1L;
    uint16_t *T1H, *T1L, *T2H, *T2L, *T3H, *T3L, *HH, *HL, *Wh, *Wl;
    float *PS, *SG, *bcat;
    cudaGetSymbolAddress((void**)&obsH, g_obsH);
    cudaGetSymbolAddress((void**)&obsL, g_obsL);
    cudaGetSymbolAddress((void**)&S1H, g_S1H);
    cudaGetSymbolAddress((void**)&S1L, g_S1L);
    cudaGetSymbolAddress((void**)&T1H, g_T1H);
    cudaGetSymbolAddress((void**)&T1L, g_T1L);
    cudaGetSymbolAddress((void**)&T2H, g_T2H);
    cudaGetSymbolAddress((void**)&T2L, g_T2L);
    cudaGetSymbolAddress((void**)&T3H, g_T3H);
    cudaGetSymbolAddress((void**)&T3L, g_T3L);
    cudaGetSymbolAddress((void**)&HH, g_HH);
    cudaGetSymbolAddress((void**)&HL, g_HL);
    cudaGetSymbolAddress((void**)&Wh, g_Wh);
    cudaGetSymbolAddress((void**)&Wl, g_Wl);
    cudaGetSymbolAddress((void**)&PS, g_PS);
    cudaGetSymbolAddress((void**)&SG, g_SG);
    cudaGetSymbolAddress((void**)&bcat, g_bcat);

    cudaFuncSetAttribute(gemm_tc3<128>, cudaFuncAttributeMaxDynamicSharedMemorySize, SMEM128);
    cudaFuncSetAttribute(gemm_tc3<64>,  cudaFuncAttributeMaxDynamicSharedMemorySize, SMEM64);

    // lazy-created streams/events (resources only; the launched WORK below is
    // identical and deterministic on every call)
    static cudaStream_t sA = nullptr, sB = nullptr;
    static cudaEvent_t evRoot = nullptr, evL1a = nullptr, evA = nullptr, evB = nullptr;
    if (sA == nullptr) {
        cudaStreamCreateWithFlags(&sA, cudaStreamNonBlocking);
        cudaStreamCreateWithFlags(&sB, cudaStreamNonBlocking);
        cudaEventCreateWithFlags(&evRoot, cudaEventDisableTiming);
        cudaEventCreateWithFlags(&evL1a, cudaEventDisableTiming);
        cudaEventCreateWithFlags(&evA, cudaEventDisableTiming);
        cudaEventCreateWithFlags(&evB, cudaEventDisableTiming);
    }

    // ---- prep ----
    WPack wp{};
    int e = 0;
    wp.d[e++] = {W1,  512, 512, 1024, O_W1s,       256 * 512};
    wp.d[e++] = {Ws1, 512, 512, 1024, O_W1s + 512, 256 * 512};
    wp.d[e++] = {Wg1, 512, 512, 512,  O_Wg1, 128 * 512};
    wp.d[e++] = {W2,  256, 256, 256,  O_W2,  512 * 256};
    wp.d[e++] = {Ws2, 256, 256, 256,  O_Ws2, 512 * 256};
    wp.d[e++] = {Wg2, 256, 256, 256,  O_Wg2, 512 * 256};
    wp.d[e++] = {Ws3, 128, 128, 128,  O_Ws3, 256 * 128};
    wp.d[e++] = {Wg3, 128, 128, 128,  O_Wg3, 256 * 128};
    for (int p = 0; p < 8; p++)
        wp.d[e++] = {Wp1 + (size_t)p * 65536, 256, 256, 2048,
                     O_Wp1 + (size_t)p * 256, 256 * 256};
    for (int p = 0; p < 8; p++)
        wp.d[e++] = {Wp2 + (size_t)p * 10240, 40, 64, 64,
                     O_Wp2 + (size_t)p * 16384, 256 * 64};
    wp.cnt = e;
    prep_weights<<<512, 256>>>(wp);
    size_t n4 = (size_t)BB * 384 / 4;
    prep_obs<<<(unsigned)((n4 + 255) / 256), 256>>>(obs, n4);
    prep_bias<<<4, 256>>>(b1, bs1);

    dim3 blk(256);

    // fork: root event after prep
    cudaEventRecord(evRoot, 0);
    cudaStreamWaitEvent(sA, evRoot, 0);
    cudaStreamWaitEvent(sB, evRoot, 0);

    // -------- stream sB: goal branch --------
    // L1b. Wg1: obs_goal (K=128) -> S1 cols 1024-1535
    gemm_tc3<128><<<dim3(4, 512), blk, SMEM128, sB>>>(obsH + 256, obsL + 256, 384,
        Wh + O_Wg1, Wl + O_Wg1, 512, bg1, 512,
        nullptr, S1H + 1024, S1L + 1024, 1536, 128, 1, 1, 0, 0, 0, 0);
    // L2c. Wg2: S1[:,1024:1536] -> T3
    gemm_tc3<128><<<dim3(2, 512), blk, SMEM128, sB>>>(S1H + 1024, S1L + 1024, 1536,
        Wh + O_Wg2, Wl + O_Wg2, 256, bg2, 256,
        nullptr, T3H, T3L, 256, 512, 1, 1, 0, 0, 0, 0);
    // SGb. Wg3: T3 -> SG[:,128:256] (fp32)
    gemm_tc3<128><<<dim3(1, 512), blk, SMEM128, sB>>>(T3H, T3L, 256,
        Wh + O_Wg3, Wl + O_Wg3, 128, bg3, 128,
        SG + 128, nullptr, nullptr, 256, 256, 0, 0, 0, 0, 0, 0);
    cudaEventRecord(evB, sB);

    // -------- main stream: trunk --------
    // L1a. [W1|Ws1]: obs_stat (K=256) -> S1 cols 0-1023
    gemm_tc3<128><<<dim3(8, 512), blk, SMEM128>>>(obsH, obsL, 384,
        Wh + O_W1s, Wl + O_W1s, 1024, bcat, 1024,
        nullptr, S1H, S1L, 1536, 256, 1, 1, 0, 0, 0, 0);
    cudaEventRecord(evL1a, 0);

    // -------- stream sA: stat-gate branch (needs L1a) --------
    cudaStreamWaitEvent(sA, evL1a, 0);
    // L2b. Ws2: S1[:,512:1024] -> T2
    gemm_tc3<128><<<dim3(2, 512), blk, SMEM128, sA>>>(S1H + 512, S1L + 512, 1536,
        Wh + O_Ws2, Wl + O_Ws2, 256, bs2, 256,
        nullptr, T2H, T2L, 256, 512, 1, 1, 0, 0, 0, 0);
    // SGa. Ws3: T2 -> SG[:,0:128] (fp32)
    gemm_tc3<128><<<dim3(1, 512), blk, SMEM128, sA>>>(T2H, T2L, 256,
        Wh + O_Ws3, Wl + O_Ws3, 128, bs3, 128,
        SG, nullptr, nullptr, 256, 256, 0, 0, 0, 0, 0, 0);
    cudaEventRecord(evA, sA);

    // -------- main stream continues --------
    // L2a. W2: S1[:,0:512] -> T1
    gemm_tc3<128><<<dim3(2, 512), blk, SMEM128>>>(S1H, S1L, 1536,
        Wh + O_W2, Wl + O_W2, 256, b2, 256,
        nullptr, T1H, T1L, 256, 512, 1, 1, 0, 0, 0, 0);
    // L3. Wp1 (8 heads concat on N): T1 -> H (N=2048)
    gemm_tc3<128><<<dim3(16, 512), blk, SMEM128>>>(T1H, T1L, 256,
        Wh + O_Wp1, Wl + O_Wp1, 2048, bp1, 2048,
        nullptr, HH, HL, 2048, 256, 1, 1, 0, 0, 0, 0);
    // L4. Wp2 batched z=8: H[:, p*256:(p+1)*256] -> PS[p]
    gemm_tc3<64><<<dim3(1, 512, 8), blk, SMEM64>>>(HH, HL, 2048,
        Wh + O_Wp2, Wl + O_Wp2, 64, bp2, 40,
        PS, nullptr, nullptr, 40, 256, 0, 0,
        256, 16384, (size_t)BB * 40, 40);

    // join branches, then finalize
    cudaStreamWaitEvent(0, evA, 0);
    cudaStreamWaitEvent(0, evB, 0);
    finalize_kernel<<<BB / 8, blk>>>(SG, PS, actions, Wgate, bgate, (float*)d_out);
}

// round 9
// speedup vs baseline: 2.4583x; 1.0458x over previous
#include <cuda_runtime.h>
#include <cuda_bf16.h>
#include <cstdint>

// ---------------------------------------------------------------------------
#define BB 65536
static constexpr float LRELU = 0.01f;
static constexpr float LOG_SQRT_2PI_C = 0.91893853320467274178f;

// ---------------------------------------------------------------------------
// Device scratch
// ---------------------------------------------------------------------------
__device__ uint16_t g_obsH[(size_t)BB * 384];
__device__ uint16_t g_obsL[(size_t)BB * 384];
__device__ uint16_t g_S1H[(size_t)BB * 1536];   // [W1|Ws1|Wg1] outputs
__device__ uint16_t g_S1L[(size_t)BB * 1536];
__device__ uint16_t g_T1H[(size_t)BB * 256];    // trunk2 out
__device__ uint16_t g_T1L[(size_t)BB * 256];
__device__ uint16_t g_T2H[(size_t)BB * 256];    // stat2 out
__device__ uint16_t g_T2L[(size_t)BB * 256];
__device__ uint16_t g_T3H[(size_t)BB * 256];    // goal2 out
__device__ uint16_t g_T3L[(size_t)BB * 256];
__device__ uint16_t g_HH[(size_t)BB * 2048];    // 8 heads concat on N
__device__ uint16_t g_HL[(size_t)BB * 2048];
__device__ float g_PS[(size_t)8 * BB * 40];
__device__ float g_SG[(size_t)BB * 256];
__device__ float g_bcat[1024];

static constexpr size_t WPOOL = 1441792;
__device__ uint16_t g_Wh[WPOOL];
__device__ uint16_t g_Wl[WPOOL];

// weight pool offsets
static constexpr size_t O_W1s = 0;         // 256 x 1024  ([W1|Ws1])
static constexpr size_t O_Wg1 = 262144;    // 128 x 512
static constexpr size_t O_W2  = 327680;    // 512 x 256
static constexpr size_t O_Ws2 = 458752;    // 512 x 256
static constexpr size_t O_Wg2 = 589824;    // 512 x 256
static constexpr size_t O_Ws3 = 720896;    // 256 x 128
static constexpr size_t O_Wg3 = 753664;    // 256 x 128
static constexpr size_t O_Wp1 = 786432;    // 256 x 2048 (heads on N)
static constexpr size_t O_Wp2 = 1310720;   // 8 x (256 x 64 pad)

// ---------------------------------------------------------------------------
// PTX helpers
// ---------------------------------------------------------------------------
__device__ __forceinline__ uint32_t smem_u32(const void* p) {
    uint32_t a;
    asm("{ .reg .u64 t; cvta.to.shared.u64 t, %1; cvt.u32.u64 %0, t; }"
        : "=r"(a) : "l"(p));
    return a;
}
__device__ __forceinline__ void cpa16(uint32_t dst, const void* src) {
    asm volatile("cp.async.cg.shared.global [%0], [%1], 16;"
                 :: "r"(dst), "l"(src) : "memory");
}
__device__ __forceinline__ void cp_commit() {
    asm volatile("cp.async.commit_group;" ::: "memory");
}
template <int N> __device__ __forceinline__ void cp_wait() {
    asm volatile("cp.async.wait_group %0;" :: "n"(N) : "memory");
}
__device__ __forceinline__ void ldsm4(uint32_t* r, uint32_t addr) {
    asm volatile("ldmatrix.sync.aligned.m8n8.x4.shared.b16 {%0,%1,%2,%3}, [%4];"
                 : "=r"(r[0]), "=r"(r[1]), "=r"(r[2]), "=r"(r[3]) : "r"(addr));
}
__device__ __forceinline__ void ldsm4t(uint32_t* r, uint32_t addr) {
    asm volatile("ldmatrix.sync.aligned.m8n8.x4.trans.shared.b16 {%0,%1,%2,%3}, [%4];"
                 : "=r"(r[0]), "=r"(r[1]), "=r"(r[2]), "=r"(r[3]) : "r"(addr));
}
__device__ __forceinline__ void mma_bf16(float* d, const uint32_t* a, const uint32_t* b) {
    asm volatile(
        "mma.sync.aligned.m16n8k16.row.col.f32.bf16.bf16.f32 "
        "{%0,%1,%2,%3}, {%4,%5,%6,%7}, {%8,%9}, {%0,%1,%2,%3};"
        : "+f"(d[0]), "+f"(d[1]), "+f"(d[2]), "+f"(d[3])
        : "r"(a[0]), "r"(a[1]), "r"(a[2]), "r"(a[3]), "r"(b[0]), "r"(b[1]));
}
__device__ __forceinline__ uint32_t pack_bf2(float a, float b) {
    __nv_bfloat162 h = __floats2bfloat162_rn(a, b);
    return *reinterpret_cast<uint32_t*>(&h);
}
__device__ __forceinline__ uint16_t bfh(float v) {
    __nv_bfloat16 h = __float2bfloat16_rn(v);
    return *reinterpret_cast<uint16_t*>(&h);
}
__device__ __forceinline__ float bff(uint16_t u) {
    __nv_bfloat16 h = *reinterpret_cast<__nv_bfloat16*>(&u);
    return __bfloat162float(h);
}

// ---------------------------------------------------------------------------
// Prep: split fp32 -> bf16 hi/lo planes with flexible dst layout
// ---------------------------------------------------------------------------
struct WDesc { const float* src; int N, Np, ldn; size_t off; int tot; };
struct WPack { WDesc d[24]; int cnt; };

__global__ void prep_weights(WPack p) {
    for (int e = 0; e < p.cnt; e++) {
        const WDesc w = p.d[e];
        for (int i = blockIdx.x * blockDim.x + threadIdx.x; i < w.tot;
             i += gridDim.x * blockDim.x) {
            int k = i / w.Np, n = i % w.Np;
            float v = (n < w.N) ? w.src[(size_t)k * w.N + n] : 0.f;
            uint16_t h = bfh(v);
            size_t dst = w.off + (size_t)k * w.ldn + n;
            g_Wh[dst] = h;
            g_Wl[dst] = bfh(v - bff(h));
        }
    }
}

__global__ void prep_obs(const float* __restrict__ src, size_t n4) {
    size_t i = (size_t)blockIdx.x * blockDim.x + threadIdx.x;
    if (i >= n4) return;
    float4 v = ((const float4*)src)[i];
    float h0 = bff(bfh(v.x)), h1 = bff(bfh(v.y));
    float h2 = bff(bfh(v.z)), h3 = bff(bfh(v.w));
    uint32_t* dh = (uint32_t*)&g_obsH[i * 4];
    uint32_t* dl = (uint32_t*)&g_obsL[i * 4];
    dh[0] = pack_bf2(h0, h1); dh[1] = pack_bf2(h2, h3);
    dl[0] = pack_bf2(v.x - h0, v.y - h1); dl[1] = pack_bf2(v.z - h2, v.w - h3);
}

__global__ void prep_bias(const float* __restrict__ b1, const float* __restrict__ bs1) {
    int i = blockIdx.x * blockDim.x + threadIdx.x;
    if (i < 512) g_bcat[i] = b1[i];
    else if (i < 1024) g_bcat[i] = bs1[i - 512];
}

// ---------------------------------------------------------------------------
// Split-bf16 GEMM, CTA tile 128 x NT, warp tile 32 x NT/2, K-chunk 32,
// 2-stage cp.async ring, 2 CTAs/SM. mode 0: fp32 out; mode 1: split bf16 out.
// ---------------------------------------------------------------------------
template <int NT>
__global__ void __launch_bounds__(256, 2) gemm_tc3(
    const uint16_t* __restrict__ Ah, const uint16_t* __restrict__ Al, int lda,
    const uint16_t* __restrict__ Bh, const uint16_t* __restrict__ Bl, int ldb,
    const float* __restrict__ bias, int Nreal,
    float* __restrict__ Cf, uint16_t* __restrict__ Chi, uint16_t* __restrict__ Clo,
    int ldc, int K, int act, int mode,
    size_t strideAz, size_t strideBz, size_t strideCz, int biasStride)
{
    constexpr int WN   = NT / 2;
    constexpr int NI   = WN / 8;
    constexpr int BST  = NT + 8;
    constexpr int SM_AL = 10240;
    constexpr int SM_BH = 20480;
    constexpr int SM_BL = 20480 + 32 * BST * 2;
    constexpr int STAGE = 20480 + 2 * 32 * BST * 2;
    constexpr int S = 2;

    extern __shared__ __align__(16) char smem[];
    const uint32_t sb = smem_u32(smem);

    const int t    = threadIdx.x;
    const int lane = t & 31;
    const int wid  = t >> 5;
    const int wm   = wid & 3;
    const int wn   = wid >> 2;
    const int m0   = blockIdx.y * 128;
    const int n0   = blockIdx.x * NT;
    const int z    = blockIdx.z;

    const uint16_t* Abase_h = Ah + (size_t)z * strideAz;
    const uint16_t* Abase_l = Al + (size_t)z * strideAz;
    const uint16_t* Bbase_h = Bh + (size_t)z * strideBz;
    const uint16_t* Bbase_l = Bl + (size_t)z * strideBz;
    const float*    biasp   = bias + (size_t)z * biasStride;

    auto issue = [&](int c, int buf) {
        const uint32_t base = sb + buf * STAGE;
        const int k0 = c << 5;
#pragma unroll
        for (int j = 0; j < 2; j++) {
            int i = t + 256 * j;
            int ar = i >> 2, as = i & 3;
            uint32_t off = (ar * 40 + as * 8) * 2;
            const uint16_t* sh = Abase_h + (size_t)(m0 + ar) * lda + k0 + as * 8;
            const uint16_t* sl = Abase_l + (size_t)(m0 + ar) * lda + k0 + as * 8;
            cpa16(base + off, sh);
            cpa16(base + SM_AL + off, sl);
        }
#pragma unroll
        for (int j = 0; j < NT / 64; j++) {
            int i = t + 256 * j;
            int br = i / (NT / 8), bs = i % (NT / 8);
            uint32_t off = (br * BST + bs * 8) * 2;
            const uint16_t* sh = Bbase_h + (size_t)(k0 + br) * ldb + n0 + bs * 8;
            const uint16_t* sl = Bbase_l + (size_t)(k0 + br) * ldb + n0 + bs * 8;
            cpa16(base + SM_BH + off, sh);
            cpa16(base + SM_BL + off, sl);
        }
    };

    float acc[2][NI][4];
#pragma unroll
    for (int i = 0; i < 2; i++)
#pragma unroll
        for (int j = 0; j < NI; j++)
#pragma unroll
            for (int q = 0; q < 4; q++) acc[i][j][q] = 0.f;

    const int nch = K >> 5;
    issue(0, 0);
    cp_commit();

    for (int c = 0; c < nch; c++) {
        if (c + 1 < nch) {
            issue(c + 1, (c + 1) & 1);
            cp_commit();
            cp_wait<1>();
        } else {
            cp_wait<0>();
        }
        __syncthreads();

        const uint32_t base = sb + (c & 1) * STAGE;
#pragma unroll
        for (int ks = 0; ks < 32; ks += 16) {
            uint32_t Afh[2][4], Afl[2][4], Bfh[NI][2], Bfl[NI][2];
            {
                int r  = lane & 15;
                int kq = (lane >> 4) * 8;
#pragma unroll
                for (int mi = 0; mi < 2; mi++) {
                    int m = wm * 32 + mi * 16 + r;
                    uint32_t off = (m * 40 + ks + kq) * 2;
                    ldsm4(Afh[mi], base + off);
                    ldsm4(Afl[mi], base + SM_AL + off);
                }
            }
            {
                int g  = lane >> 3;
                int rr = lane & 7;
                int krow = ks + (g & 1) * 8 + rr;
                int ncol = (g >> 1) * 8;
#pragma unroll
                for (int blk = 0; blk < NI / 2; blk++) {
                    int nb = wn * WN + blk * 16 + ncol;
                    uint32_t off = (krow * BST + nb) * 2;
                    ldsm4t(&Bfh[blk * 2][0], base + SM_BH + off);
                    ldsm4t(&Bfl[blk * 2][0], base + SM_BL + off);
                }
            }
#pragma unroll
            for (int mi = 0; mi < 2; mi++)
#pragma unroll
                for (int ni = 0; ni < NI; ni++) {
                    mma_bf16(acc[mi][ni], Afh[mi], Bfh[ni]);
                    mma_bf16(acc[mi][ni], Afh[mi], Bfl[ni]);
                    mma_bf16(acc[mi][ni], Afl[mi], Bfh[ni]);
                }
        }
        __syncthreads();
    }

    // ---- epilogue ----
    const int r4 = lane >> 2;
    const int c2 = (lane & 3) * 2;
#pragma unroll
    for (int mi = 0; mi < 2; mi++) {
#pragma unroll
        for (int ni = 0; ni < NI; ni++) {
            int col = n0 + wn * WN + ni * 8 + c2;
            int row = m0 + wm * 32 + mi * 16 + r4;
            if (mode == 0 && col >= Nreal) continue;
            float b0 = biasp[col], b1 = biasp[col + 1];
            float v0 = acc[mi][ni][0] + b0;
            float v1 = acc[mi][ni][1] + b1;
            float v2 = acc[mi][ni][2] + b0;
            float v3 = acc[mi][ni][3] + b1;
            if (act) {
                v0 = v0 > 0.f ? v0 : LRELU * v0;
                v1 = v1 > 0.f ? v1 : LRELU * v1;
                v2 = v2 > 0.f ? v2 : LRELU * v2;
                v3 = v3 > 0.f ? v3 : LRELU * v3;
            }
            size_t i0 = (size_t)z * strideCz + (size_t)row * ldc + col;
            size_t i1 = (size_t)z * strideCz + (size_t)(row + 8) * ldc + col;
            if (mode == 0) {
                *(float2*)&Cf[i0] = make_float2(v0, v1);
                *(float2*)&Cf[i1] = make_float2(v2, v3);
            } else {
                float h0 = bff(bfh(v0)), h1 = bff(bfh(v1));
                float h2 = bff(bfh(v2)), h3 = bff(bfh(v3));
                *(uint32_t*)&Chi[i0] = pack_bf2(h0, h1);
                *(uint32_t*)&Clo[i0] = pack_bf2(v0 - h0, v1 - h1);
                *(uint32_t*)&Chi[i1] = pack_bf2(h2, h3);
                *(uint32_t*)&Clo[i1] = pack_bf2(v2 - h2, v3 - h3);
            }
        }
    }
}

// ---------------------------------------------------------------------------
// Finalize
// ---------------------------------------------------------------------------
__global__ __launch_bounds__(256) void finalize_kernel(
    const float* __restrict__ SG, const float* __restrict__ PS,
    const float* __restrict__ actions,
    const float* __restrict__ Wgate, const float* __restrict__ bgate,
    float* __restrict__ out)
{
    __shared__ float Wg_s[8 * 256];
    const int t = threadIdx.x;
    for (int i = t; i < 2048; i += 256) {
        int k = i >> 3, p = i & 7;
        Wg_s[p * 256 + k] = Wgate[i];
    }
    __syncthreads();

    const int warp = t >> 5, lane = t & 31;
    const size_t row = (size_t)blockIdx.x * 8 + warp;

    float accp[8] = {0, 0, 0, 0, 0, 0, 0, 0};
#pragma unroll
    for (int i = 0; i < 8; i++) {
        float v = SG[row * 256 + lane + 32 * i];
        v = v > 0.f ? v : LRELU * v;
#pragma unroll
        for (int p = 0; p < 8; p++)
            accp[p] += v * Wg_s[p * 256 + lane + 32 * i];
    }
#pragma unroll
    for (int off = 16; off; off >>= 1)
#pragma unroll
        for (int p = 0; p < 8; p++)
            accp[p] += __shfl_xor_sync(0xffffffffu, accp[p], off);

    float wg[8];
#pragma unroll
    for (int p = 0; p < 8; p++)
        wg[p] = expf(accp[p] + bgate[p]);

    float lp = 0.f, ent = 0.f;
    if (lane < 20) {
        float s1 = 0.f, s2 = 0.f;
#pragma unroll
        for (int p = 0; p < 8; p++) {
            const float* psr = PS + ((size_t)p * BB + row) * 40;
            float mu = psr[lane];
            float lg = psr[20 + lane];
            float inv = wg[p] * expf(-lg);
            s1 += mu * inv;
            s2 += inv;
        }
        float a = actions[row * 20 + lane];
        float z = (a - s1 / s2) * s2;
        float logsig = -logf(s2);
        lp  = -0.5f * z * z - logsig - LOG_SQRT_2PI_C;
        ent = 0.5f + LOG_SQRT_2PI_C + logsig;
    }
#pragma unroll
    for (int off = 16; off; off >>= 1) {
        lp  += __shfl_xor_sync(0xffffffffu, lp,  off);
        ent += __shfl_xor_sync(0xffffffffu, ent, off);
    }
    if (lane == 0) {
        out[row * 2]     = lp;
        out[row * 2 + 1] = ent;
    }
}

// ---------------------------------------------------------------------------
// Launcher with stream fork/join (graph-capturable DAG)
// ---------------------------------------------------------------------------
static constexpr int SMEM128 = 2 * (20480 + 2 * 32 * 136 * 2);  // 75776
static constexpr int SMEM64  = 2 * (20480 + 2 * 32 * 72 * 2);   // 59392

extern "C" void kernel_launch(void* const* d_in, const int* in_sizes, int n_in,
                              void* d_out, int out_size)
{
    const float* obs     = (const float*)d_in[0];
    const float* actions = (const float*)d_in[1];
    const float* W1      = (const float*)d_in[2];
    const float* b1      = (const float*)d_in[3];
    const float* W2      = (const float*)d_in[4];
    const float* b2      = (const float*)d_in[5];
    const float* Wp1     = (const float*)d_in[6];
    const float* bp1     = (const float*)d_in[7];
    const float* Wp2     = (const float*)d_in[8];
    const float* bp2     = (const float*)d_in[9];
    const float* Ws1     = (const float*)d_in[10];
    const float* bs1     = (const float*)d_in[11];
    const float* Ws2     = (const float*)d_in[12];
    const float* bs2     = (const float*)d_in[13];
    const float* Ws3     = (const float*)d_in[14];
    const float* bs3     = (const float*)d_in[15];
    const float* Wg1     = (const float*)d_in[16];
    const float* bg1     = (const float*)d_in[17];
    const float* Wg2     = (const float*)d_in[18];
    const float* bg2     = (const float*)d_in[19];
    const float* Wg3     = (const float*)d_in[20];
    const float* bg3     = (const float*)d_in[21];
    const float* Wgate   = (const float*)d_in[22];
    const float* bgate   = (const float*)d_in[23];

    uint16_t *obsH, *obsL, *S1H, *S1L;
    uint16_t *T1H, *T1L, *T2H, *T2L, *T3H, *T3L, *HH, *HL, *Wh, *Wl;
    float *PS, *SG, *bcat;
    cudaGetSymbolAddress((void**)&obsH, g_obsH);
    cudaGetSymbolAddress((void**)&obsL, g_obsL);
    cudaGetSymbolAddress((void**)&S1H, g_S1H);
    cudaGetSymbolAddress((void**)&S1L, g_S1L);
    cudaGetSymbolAddress((void**)&T1H, g_T1H);
    cudaGetSymbolAddress((void**)&T1L, g_T1L);
    cudaGetSymbolAddress((void**)&T2H, g_T2H);
    cudaGetSymbolAddress((void**)&T2L, g_T2L);
    cudaGetSymbolAddress((void**)&T3H, g_T3H);
    cudaGetSymbolAddress((void**)&T3L, g_T3L);
    cudaGetSymbolAddress((void**)&HH, g_HH);
    cudaGetSymbolAddress((void**)&HL, g_HL);
    cudaGetSymbolAddress((void**)&Wh, g_Wh);
    cudaGetSymbolAddress((void**)&Wl, g_Wl);
    cudaGetSymbolAddress((void**)&PS, g_PS);
    cudaGetSymbolAddress((void**)&SG, g_SG);
    cudaGetSymbolAddress((void**)&bcat, g_bcat);

    cudaFuncSetAttribute(gemm_tc3<128>, cudaFuncAttributeMaxDynamicSharedMemorySize, SMEM128);
    cudaFuncSetAttribute(gemm_tc3<64>,  cudaFuncAttributeMaxDynamicSharedMemorySize, SMEM64);

    static cudaStream_t sA = nullptr, sB = nullptr;
    static cudaEvent_t evRoot = nullptr, evL1a = nullptr, evA = nullptr, evB = nullptr;
    if (sA == nullptr) {
        cudaStreamCreateWithFlags(&sA, cudaStreamNonBlocking);
        cudaStreamCreateWithFlags(&sB, cudaStreamNonBlocking);
        cudaEventCreateWithFlags(&evRoot, cudaEventDisableTiming);
        cudaEventCreateWithFlags(&evL1a, cudaEventDisableTiming);
        cudaEventCreateWithFlags(&evA, cudaEventDisableTiming);
        cudaEventCreateWithFlags(&evB, cudaEventDisableTiming);
    }

    // ---- prep ----
    WPack wp{};
    int e = 0;
    wp.d[e++] = {W1,  512, 512, 1024, O_W1s,       256 * 512};
    wp.d[e++] = {Ws1, 512, 512, 1024, O_W1s + 512, 256 * 512};
    wp.d[e++] = {Wg1, 512, 512, 512,  O_Wg1, 128 * 512};
    wp.d[e++] = {W2,  256, 256, 256,  O_W2,  512 * 256};
    wp.d[e++] = {Ws2, 256, 256, 256,  O_Ws2, 512 * 256};
    wp.d[e++] = {Wg2, 256, 256, 256,  O_Wg2, 512 * 256};
    wp.d[e++] = {Ws3, 128, 128, 128,  O_Ws3, 256 * 128};
    wp.d[e++] = {Wg3, 128, 128, 128,  O_Wg3, 256 * 128};
    for (int p = 0; p < 8; p++)
        wp.d[e++] = {Wp1 + (size_t)p * 65536, 256, 256, 2048,
                     O_Wp1 + (size_t)p * 256, 256 * 256};
    for (int p = 0; p < 8; p++)
        wp.d[e++] = {Wp2 + (size_t)p * 10240, 40, 64, 64,
                     O_Wp2 + (size_t)p * 16384, 256 * 64};
    wp.cnt = e;
    prep_weights<<<512, 256>>>(wp);
    size_t n4 = (size_t)BB * 384 / 4;
    prep_obs<<<(unsigned)((n4 + 255) / 256), 256>>>(obs, n4);
    prep_bias<<<4, 256>>>(b1, bs1);

    dim3 blk(256);

    // fork: root event after prep
    cudaEventRecord(evRoot, 0);
    cudaStreamWaitEvent(sA, evRoot, 0);
    cudaStreamWaitEvent(sB, evRoot, 0);

    // -------- stream sB: goal branch --------
    gemm_tc3<128><<<dim3(4, 512), blk, SMEM128, sB>>>(obsH + 256, obsL + 256, 384,
        Wh + O_Wg1, Wl + O_Wg1, 512, bg1, 512,
        nullptr, S1H + 1024, S1L + 1024, 1536, 128, 1, 1, 0, 0, 0, 0);
    gemm_tc3<128><<<dim3(2, 512), blk, SMEM128, sB>>>(S1H + 1024, S1L + 1024, 1536,
        Wh + O_Wg2, Wl + O_Wg2, 256, bg2, 256,
        nullptr, T3H, T3L, 256, 512, 1, 1, 0, 0, 0, 0);
    gemm_tc3<128><<<dim3(1, 512), blk, SMEM128, sB>>>(T3H, T3L, 256,
        Wh + O_Wg3, Wl + O_Wg3, 128, bg3, 128,
        SG + 128, nullptr, nullptr, 256, 256, 0, 0, 0, 0, 0, 0);
    cudaEventRecord(evB, sB);

    // -------- main stream: trunk --------
    gemm_tc3<128><<<dim3(8, 512), blk, SMEM128>>>(obsH, obsL, 384,
        Wh + O_W1s, Wl + O_W1s, 1024, bcat, 1024,
        nullptr, S1H, S1L, 1536, 256, 1, 1, 0, 0, 0, 0);
    cudaEventRecord(evL1a, 0);

    // -------- stream sA: stat-gate branch --------
    cudaStreamWaitEvent(sA, evL1a, 0);
    gemm_tc3<128><<<dim3(2, 512), blk, SMEM128, sA>>>(S1H + 512, S1L + 512, 1536,
        Wh + O_Ws2, Wl + O_Ws2, 256, bs2, 256,
        nullptr, T2H, T2L, 256, 512, 1, 1, 0, 0, 0, 0);
    gemm_tc3<128><<<dim3(1, 512), blk, SMEM128, sA>>>(T2H, T2L, 256,
        Wh + O_Ws3, Wl + O_Ws3, 128, bs3, 128,
        SG, nullptr, nullptr, 256, 256, 0, 0, 0, 0, 0, 0);
    cudaEventRecord(evA, sA);

    // -------- main stream continues --------
    gemm_tc3<128><<<dim3(2, 512), blk, SMEM128>>>(S1H, S1L, 1536,
        Wh + O_W2, Wl + O_W2, 256, b2, 256,
        nullptr, T1H, T1L, 256, 512, 1, 1, 0, 0, 0, 0);
    gemm_tc3<128><<<dim3(16, 512), blk, SMEM128>>>(T1H, T1L, 256,
        Wh + O_Wp1, Wl + O_Wp1, 2048, bp1, 2048,
        nullptr, HH, HL, 2048, 256, 1, 1, 0, 0, 0, 0);
    gemm_tc3<64><<<dim3(1, 512, 8), blk, SMEM64>>>(HH, HL, 2048,
        Wh + O_Wp2, Wl + O_Wp2, 64, bp2, 40,
        PS, nullptr, nullptr, 40, 256, 0, 0,
        256, 16384, (size_t)BB * 40, 40);

    // join branches, then finalize
    cudaStreamWaitEvent(0, evA, 0);
    cudaStreamWaitEvent(0, evB, 0);
    finalize_kernel<<<BB / 8, blk>>>(SG, PS, actions, Wgate, bgate, (float*)d_out);
}